// round 1
// baseline (speedup 1.0000x reference)
#include <cuda_runtime.h>
#include <math.h>

#define B_  4
#define S_  2048
#define D_  1024
#define H_  16
#define DK_ 64
#define M_  (B_*S_)

// Scratch (allocation-free rule: __device__ globals)
__device__ float g_q[(size_t)M_*D_];   // [b,h,s,dk]
__device__ float g_k[(size_t)M_*D_];   // [b,h,s,dk]
__device__ float g_v[(size_t)M_*D_];   // [b,h,s,dk]
__device__ float g_o[(size_t)M_*D_];   // [b,s, h*64+d] == [8192,1024] row-major

// ---------------------------------------------------------------------------
// GEMM: Y = X @ W^T + bias     X:[8192,1024] row-major, W:[1024,1024] row-major
// MODE 0: Y row-major [m][n]           (final output projection)
// MODE 1: Y in head layout [b,h,s,dk]  (Q/K/V projections)
// ---------------------------------------------------------------------------
template<int MODE>
__device__ __forceinline__ void gemm_body(const float* __restrict__ X,
                                          const float* __restrict__ W,
                                          const float* __restrict__ bias,
                                          float* __restrict__ Y)
{
    constexpr int BM = 128, BN = 128, BK = 8;
    __shared__ float As[BK][BM + 4];
    __shared__ float Bs[BK][BN + 4];

    const int tid  = threadIdx.x;          // 256 threads
    const int tx   = tid & 15;
    const int ty   = tid >> 4;
    const int row0 = blockIdx.y * BM;
    const int col0 = blockIdx.x * BN;
    const int lr   = tid >> 1;             // 0..127
    const int lc   = (tid & 1) * 4;        // 0 or 4

    float acc[8][8];
#pragma unroll
    for (int i = 0; i < 8; i++)
#pragma unroll
        for (int j = 0; j < 8; j++) acc[i][j] = 0.f;

    const float* Xp = X + (size_t)(row0 + lr) * D_ + lc;
    const float* Wp = W + (size_t)(col0 + lr) * D_ + lc;

    for (int k0 = 0; k0 < D_; k0 += BK) {
        float4 a = *(const float4*)(Xp + k0);
        float4 b = *(const float4*)(Wp + k0);
        __syncthreads();
        As[lc + 0][lr] = a.x; As[lc + 1][lr] = a.y;
        As[lc + 2][lr] = a.z; As[lc + 3][lr] = a.w;
        Bs[lc + 0][lr] = b.x; Bs[lc + 1][lr] = b.y;
        Bs[lc + 2][lr] = b.z; Bs[lc + 3][lr] = b.w;
        __syncthreads();
#pragma unroll
        for (int kk = 0; kk < BK; kk++) {
            float4 a0 = *(const float4*)&As[kk][ty * 4];
            float4 a1 = *(const float4*)&As[kk][64 + ty * 4];
            float4 b0 = *(const float4*)&Bs[kk][tx * 4];
            float4 b1 = *(const float4*)&Bs[kk][64 + tx * 4];
            float ar[8] = {a0.x, a0.y, a0.z, a0.w, a1.x, a1.y, a1.z, a1.w};
            float br[8] = {b0.x, b0.y, b0.z, b0.w, b1.x, b1.y, b1.z, b1.w};
#pragma unroll
            for (int i = 0; i < 8; i++)
#pragma unroll
                for (int j = 0; j < 8; j++)
                    acc[i][j] = fmaf(ar[i], br[j], acc[i][j]);
        }
    }

#pragma unroll
    for (int ig = 0; ig < 2; ig++)
#pragma unroll
        for (int i = 0; i < 4; i++) {
            int r = row0 + ig * 64 + ty * 4 + i;
#pragma unroll
            for (int jg = 0; jg < 2; jg++) {
                int c = col0 + jg * 64 + tx * 4;
                float4 v;
                v.x = acc[ig * 4 + i][jg * 4 + 0] + bias[c + 0];
                v.y = acc[ig * 4 + i][jg * 4 + 1] + bias[c + 1];
                v.z = acc[ig * 4 + i][jg * 4 + 2] + bias[c + 2];
                v.w = acc[ig * 4 + i][jg * 4 + 3] + bias[c + 3];
                if (MODE == 0) {
                    *(float4*)&Y[(size_t)r * D_ + c] = v;
                } else {
                    int bb = r >> 11, s = r & (S_ - 1);
                    int h  = c >> 6,  d = c & 63;   // tx*4..tx*4+3 stay inside one head
                    *(float4*)&Y[(((size_t)bb * H_ + h) * S_ + s) * DK_ + d] = v;
                }
            }
        }
}

__global__ __launch_bounds__(256) void gemm_q_kernel(const float* __restrict__ X,
    const float* __restrict__ W, const float* __restrict__ b) { gemm_body<1>(X, W, b, g_q); }
__global__ __launch_bounds__(256) void gemm_k_kernel(const float* __restrict__ X,
    const float* __restrict__ W, const float* __restrict__ b) { gemm_body<1>(X, W, b, g_k); }
__global__ __launch_bounds__(256) void gemm_v_kernel(const float* __restrict__ X,
    const float* __restrict__ W, const float* __restrict__ b) { gemm_body<1>(X, W, b, g_v); }
__global__ __launch_bounds__(256) void gemm_o_kernel(const float* __restrict__ W,
    const float* __restrict__ b, float* __restrict__ Y) { gemm_body<0>(g_o, W, b, Y); }

// ---------------------------------------------------------------------------
// Flash attention (fp32): per (b,h), 64-row Q tile, 64-col KV tiles, causal.
// grid = (S/64 = 32, B*H = 64), block = 256 threads (16x16, 4x4 micro-tile).
// smem: Qs | Ks(->Ps) | Vs, each 64 x 68 floats (pad 68 kills bank conflicts).
// ---------------------------------------------------------------------------
#define LDSM 68

__global__ __launch_bounds__(256) void attn_kernel()
{
    extern __shared__ float sm[];
    float* Qs = sm;
    float* Ks = sm + 64 * LDSM;     // reused as P (transposed) after scores
    float* Vs = sm + 2 * 64 * LDSM;

    const int tid = threadIdx.x;
    const int tx  = tid & 15;
    const int ty  = tid >> 4;
    const int bh  = blockIdx.y;
    const int qt  = blockIdx.x;
    const int q0  = qt * 64;

    const float* Qb = g_q + (size_t)bh * S_ * DK_;
    const float* Kb = g_k + (size_t)bh * S_ * DK_;
    const float* Vb = g_v + (size_t)bh * S_ * DK_;

    // load Q tile (64x64) once
    {
        int r  = tid >> 2;
        int c0 = (tid & 3) * 16;
#pragma unroll
        for (int q = 0; q < 4; q++) {
            float4 v = *(const float4*)(Qb + (q0 + r) * DK_ + c0 + q * 4);
            *(float4*)&Qs[r * LDSM + c0 + q * 4] = v;
        }
    }

    float o[4][4];
    float mrow[4], lrow[4];
#pragma unroll
    for (int i = 0; i < 4; i++) {
        mrow[i] = -INFINITY; lrow[i] = 0.f;
#pragma unroll
        for (int j = 0; j < 4; j++) o[i][j] = 0.f;
    }

    for (int kt = 0; kt <= qt; kt++) {
        __syncthreads();  // prior-iter Ps/Vs consumed; also fences the Qs load on iter 0
        {
            int r  = tid >> 2;
            int c0 = (tid & 3) * 16;
            int kr = (kt * 64 + r) * DK_;
#pragma unroll
            for (int q = 0; q < 4; q++) {
                *(float4*)&Ks[r * LDSM + c0 + q * 4] = *(const float4*)(Kb + kr + c0 + q * 4);
                *(float4*)&Vs[r * LDSM + c0 + q * 4] = *(const float4*)(Vb + kr + c0 + q * 4);
            }
        }
        __syncthreads();

        // scores S = Q K^T (4x4 per thread)
        float s[4][4];
#pragma unroll
        for (int i = 0; i < 4; i++)
#pragma unroll
            for (int j = 0; j < 4; j++) s[i][j] = 0.f;

#pragma unroll
        for (int d4 = 0; d4 < 16; d4++) {
            float4 a[4], bf[4];
#pragma unroll
            for (int i = 0; i < 4; i++) a[i]  = *(const float4*)&Qs[(ty * 4 + i) * LDSM + d4 * 4];
#pragma unroll
            for (int j = 0; j < 4; j++) bf[j] = *(const float4*)&Ks[(tx * 4 + j) * LDSM + d4 * 4];
#pragma unroll
            for (int i = 0; i < 4; i++)
#pragma unroll
                for (int j = 0; j < 4; j++) {
                    s[i][j] = fmaf(a[i].x, bf[j].x, s[i][j]);
                    s[i][j] = fmaf(a[i].y, bf[j].y, s[i][j]);
                    s[i][j] = fmaf(a[i].z, bf[j].z, s[i][j]);
                    s[i][j] = fmaf(a[i].w, bf[j].w, s[i][j]);
                }
        }

        const bool diag = (kt == qt);
#pragma unroll
        for (int i = 0; i < 4; i++)
#pragma unroll
            for (int j = 0; j < 4; j++) {
                float v = s[i][j] * 0.125f;                       // 1/sqrt(64)
                if (diag && (tx * 4 + j) > (ty * 4 + i)) v = -INFINITY;
                s[i][j] = v;
            }

        // online softmax: reductions across tx (lane bits 0..3)
        float alpha[4];
#pragma unroll
        for (int i = 0; i < 4; i++) {
            float rm = fmaxf(fmaxf(s[i][0], s[i][1]), fmaxf(s[i][2], s[i][3]));
#pragma unroll
            for (int off = 1; off < 16; off <<= 1)
                rm = fmaxf(rm, __shfl_xor_sync(0xffffffffu, rm, off));
            float mnew = fmaxf(mrow[i], rm);
            float rs = 0.f;
#pragma unroll
            for (int j = 0; j < 4; j++) { s[i][j] = __expf(s[i][j] - mnew); rs += s[i][j]; }
#pragma unroll
            for (int off = 1; off < 16; off <<= 1)
                rs += __shfl_xor_sync(0xffffffffu, rs, off);
            alpha[i] = __expf(mrow[i] - mnew);
            lrow[i]  = lrow[i] * alpha[i] + rs;
            mrow[i]  = mnew;
        }
#pragma unroll
        for (int i = 0; i < 4; i++)
#pragma unroll
            for (int j = 0; j < 4; j++) o[i][j] *= alpha[i];

        __syncthreads();                 // all threads done reading Ks
        // store P transposed: Ps[c][r]
#pragma unroll
        for (int j = 0; j < 4; j++)
#pragma unroll
            for (int i = 0; i < 4; i++)
                Ks[(tx * 4 + j) * LDSM + (ty * 4 + i)] = s[i][j];
        __syncthreads();

        // O += P V
#pragma unroll 8
        for (int c = 0; c < 64; c++) {
            float4 p  = *(const float4*)&Ks[c * LDSM + ty * 4];
            float4 vv = *(const float4*)&Vs[c * LDSM + tx * 4];
            float pr[4] = {p.x, p.y, p.z, p.w};
            float vr[4] = {vv.x, vv.y, vv.z, vv.w};
#pragma unroll
            for (int i = 0; i < 4; i++)
#pragma unroll
                for (int j = 0; j < 4; j++)
                    o[i][j] = fmaf(pr[i], vr[j], o[i][j]);
        }
    }

    // epilogue: normalize, write [b, s, h*64+d]
    const int bb = bh >> 4, h = bh & 15;
#pragma unroll
    for (int i = 0; i < 4; i++) {
        float inv = 1.0f / lrow[i];
        int row = q0 + ty * 4 + i;
        float4 v = {o[i][0] * inv, o[i][1] * inv, o[i][2] * inv, o[i][3] * inv};
        *(float4*)&g_o[((size_t)bb * S_ + row) * D_ + h * DK_ + tx * 4] = v;
    }
}

// ---------------------------------------------------------------------------
extern "C" void kernel_launch(void* const* d_in, const int* in_sizes, int n_in,
                              void* d_out, int out_size)
{
    const float* x  = (const float*)d_in[0];
    const float* Wq = (const float*)d_in[1];
    const float* bq = (const float*)d_in[2];
    const float* Wk = (const float*)d_in[3];
    const float* bk = (const float*)d_in[4];
    const float* Wv = (const float*)d_in[5];
    const float* bv = (const float*)d_in[6];
    const float* Wo = (const float*)d_in[7];
    const float* bo = (const float*)d_in[8];
    float* out = (float*)d_out;

    dim3 gg(D_ / 128, M_ / 128);   // (8, 64)
    gemm_q_kernel<<<gg, 256>>>(x, Wq, bq);
    gemm_k_kernel<<<gg, 256>>>(x, Wk, bk);
    gemm_v_kernel<<<gg, 256>>>(x, Wv, bv);

    const int smem = 3 * 64 * LDSM * (int)sizeof(float);  // 52224 B
    cudaFuncSetAttribute(attn_kernel, cudaFuncAttributeMaxDynamicSharedMemorySize, smem);
    attn_kernel<<<dim3(S_ / 64, B_ * H_), 256, smem>>>();

    gemm_o_kernel<<<gg, 256>>>(Wo, bo, out);
}

// round 3
// speedup vs baseline: 1.2362x; 1.2362x over previous
#include <cuda_runtime.h>
#include <cuda_bf16.h>
#include <cstdint>
#include <math.h>

#define B_  4
#define S_  2048
#define D_  1024
#define H_  16
#define DK_ 64
#define M_  (B_*S_)

// Scratch (allocation-free rule: __device__ globals)
__device__ float g_q[(size_t)M_*D_];   // [b,h,s,dk]
__device__ float g_k[(size_t)M_*D_];   // [b,h,s,dk]
__device__ float g_v[(size_t)M_*D_];   // [b,h,s,dk]
__device__ float g_o[(size_t)M_*D_];   // [b,s, h*64+d] == [8192,1024] row-major

// ---------------------------------------------------------------------------
// Tensor-core GEMM (bf16 split-precision, 3-pass): Y = X @ W^T + bias
// ---------------------------------------------------------------------------

__device__ __forceinline__ void ldsm4(uint32_t* r, uint32_t addr)
{
    asm volatile("ldmatrix.sync.aligned.m8n8.x4.shared.b16 {%0,%1,%2,%3}, [%4];"
        : "=r"(r[0]), "=r"(r[1]), "=r"(r[2]), "=r"(r[3]) : "r"(addr));
}

__device__ __forceinline__ void mma16816(float* c, const uint32_t* a, const uint32_t* b)
{
    asm volatile("mma.sync.aligned.m16n8k16.row.col.f32.bf16.bf16.f32 "
        "{%0,%1,%2,%3}, {%4,%5,%6,%7}, {%8,%9}, {%0,%1,%2,%3};"
        : "+f"(c[0]), "+f"(c[1]), "+f"(c[2]), "+f"(c[3])
        : "r"(a[0]), "r"(a[1]), "r"(a[2]), "r"(a[3]), "r"(b[0]), "r"(b[1]));
}

#define GLDA 40   // 32 + 8 halves pad: 80B row stride -> conflict-free ldmatrix

template<int MODE>
__device__ __forceinline__ void gemm_tc(const float* __restrict__ X,
                                        const float* __restrict__ W,
                                        const float* __restrict__ bias,
                                        float* __restrict__ Y)
{
    __shared__ __nv_bfloat16 Ah[128 * GLDA];
    __shared__ __nv_bfloat16 Al[128 * GLDA];
    __shared__ __nv_bfloat16 Bh[128 * GLDA];
    __shared__ __nv_bfloat16 Bl[128 * GLDA];

    const int tid  = threadIdx.x;           // 256 threads
    const int lane = tid & 31;
    const int w    = tid >> 5;              // warp 0..7
    const int wm   = (w >> 2) * 64;         // warp M offset in 128-tile
    const int wn   = (w & 3) * 32;          // warp N offset in 128-tile
    const int row0 = blockIdx.y * 128;
    const int col0 = blockIdx.x * 128;

    float acc[4][4][4];
#pragma unroll
    for (int im = 0; im < 4; im++)
#pragma unroll
        for (int in = 0; in < 4; in++)
#pragma unroll
            for (int q = 0; q < 4; q++)
                acc[im][in][q] = 0.0f;

    const int glr = tid >> 3;               // 0..31
    const int glc = (tid & 7) * 4;          // 0,4,...,28

    const uint32_t aAh = (uint32_t)__cvta_generic_to_shared(Ah);
    const uint32_t aAl = (uint32_t)__cvta_generic_to_shared(Al);
    const uint32_t aBh = (uint32_t)__cvta_generic_to_shared(Bh);
    const uint32_t aBl = (uint32_t)__cvta_generic_to_shared(Bl);

    for (int k0 = 0; k0 < D_; k0 += 32) {
        float4 xa[4];
        float4 wa[4];
#pragma unroll
        for (int rr = 0; rr < 4; rr++) {
            int r = rr * 32 + glr;
            xa[rr] = *(const float4*)(X + (size_t)(row0 + r) * D_ + k0 + glc);
            wa[rr] = *(const float4*)(W + (size_t)(col0 + r) * D_ + k0 + glc);
        }
        __syncthreads();
#pragma unroll
        for (int rr = 0; rr < 4; rr++) {
            int r = rr * 32 + glr;
            const float* xv = (const float*)(xa + rr);
            const float* wv = (const float*)(wa + rr);
#pragma unroll
            for (int e = 0; e < 4; e++) {
                float v  = xv[e];
                __nv_bfloat16 hi = __float2bfloat16(v);
                Ah[r * GLDA + glc + e] = hi;
                Al[r * GLDA + glc + e] = __float2bfloat16(v - __bfloat162float(hi));
                v  = wv[e];
                hi = __float2bfloat16(v);
                Bh[r * GLDA + glc + e] = hi;
                Bl[r * GLDA + glc + e] = __float2bfloat16(v - __bfloat162float(hi));
            }
        }
        __syncthreads();

#pragma unroll
        for (int kc = 0; kc < 2; kc++) {
            const uint32_t colb = (uint32_t)(kc * 16 + ((lane >> 4) << 3)) * 2;
            uint32_t afh[4][4];
            uint32_t afl[4][4];
#pragma unroll
            for (int im = 0; im < 4; im++) {
                uint32_t off = (uint32_t)((wm + im * 16 + (lane & 15)) * GLDA) * 2 + colb;
                ldsm4(afh[im], aAh + off);
                ldsm4(afl[im], aAl + off);
            }
            uint32_t bfh[4][2];
            uint32_t bfl[4][2];
#pragma unroll
            for (int np = 0; np < 2; np++) {
                uint32_t off = (uint32_t)((wn + np * 16 + (lane & 15)) * GLDA) * 2 + colb;
                uint32_t r4[4];
                ldsm4(r4, aBh + off);
                bfh[np * 2 + 0][0] = r4[0];
                bfh[np * 2 + 0][1] = r4[2];
                bfh[np * 2 + 1][0] = r4[1];
                bfh[np * 2 + 1][1] = r4[3];
                ldsm4(r4, aBl + off);
                bfl[np * 2 + 0][0] = r4[0];
                bfl[np * 2 + 0][1] = r4[2];
                bfl[np * 2 + 1][0] = r4[1];
                bfl[np * 2 + 1][1] = r4[3];
            }
#pragma unroll
            for (int im = 0; im < 4; im++) {
#pragma unroll
                for (int in = 0; in < 4; in++) {
                    mma16816(acc[im][in], afh[im], bfh[in]);
                    mma16816(acc[im][in], afh[im], bfl[in]);
                    mma16816(acc[im][in], afl[im], bfh[in]);
                }
            }
        }
    }

    const int r_in = lane >> 2;
    const int c_in = (lane & 3) * 2;
#pragma unroll
    for (int im = 0; im < 4; im++) {
#pragma unroll
        for (int in = 0; in < 4; in++) {
            int rg = row0 + wm + im * 16 + r_in;
            int cg = col0 + wn + in * 8 + c_in;
            float b0 = bias[cg];
            float b1 = bias[cg + 1];
            float2 v0;
            float2 v1;
            v0.x = acc[im][in][0] + b0;
            v0.y = acc[im][in][1] + b1;
            v1.x = acc[im][in][2] + b0;
            v1.y = acc[im][in][3] + b1;
            if (MODE == 0) {
                *(float2*)(Y + (size_t)rg * D_ + cg)       = v0;
                *(float2*)(Y + (size_t)(rg + 8) * D_ + cg) = v1;
            } else {
                int hh = cg >> 6;
                int dd = cg & 63;
                int bb = rg >> 11;
                int ss = rg & (S_ - 1);
                size_t base = (((size_t)bb * H_ + hh) * S_ + ss) * DK_ + dd;
                *(float2*)(Y + base)           = v0;
                *(float2*)(Y + base + 8 * DK_) = v1;
            }
        }
    }
}

__global__ __launch_bounds__(256) void gemm_q_kernel(const float* __restrict__ X,
    const float* __restrict__ W, const float* __restrict__ b) { gemm_tc<1>(X, W, b, g_q); }
__global__ __launch_bounds__(256) void gemm_k_kernel(const float* __restrict__ X,
    const float* __restrict__ W, const float* __restrict__ b) { gemm_tc<1>(X, W, b, g_k); }
__global__ __launch_bounds__(256) void gemm_v_kernel(const float* __restrict__ X,
    const float* __restrict__ W, const float* __restrict__ b) { gemm_tc<1>(X, W, b, g_v); }
__global__ __launch_bounds__(256) void gemm_o_kernel(const float* __restrict__ W,
    const float* __restrict__ b, float* __restrict__ Y) { gemm_tc<0>(g_o, W, b, Y); }

// ---------------------------------------------------------------------------
// Flash attention (fp32): identical to round-1 version (known good).
// ---------------------------------------------------------------------------
#define LDA_ 68

__global__ __launch_bounds__(256) void attn_kernel()
{
    extern __shared__ float sm[];
    float* Qs = sm;
    float* Ks = sm + 64 * LDA_;
    float* Vs = sm + 2 * 64 * LDA_;

    const int tid = threadIdx.x;
    const int tx  = tid & 15;
    const int ty  = tid >> 4;
    const int bh  = blockIdx.y;
    const int qt  = blockIdx.x;
    const int q0  = qt * 64;

    const float* Qb = g_q + (size_t)bh * S_ * DK_;
    const float* Kb = g_k + (size_t)bh * S_ * DK_;
    const float* Vb = g_v + (size_t)bh * S_ * DK_;

    {
        int r  = tid >> 2;
        int c0 = (tid & 3) * 16;
#pragma unroll
        for (int q = 0; q < 4; q++) {
            float4 v = *(const float4*)(Qb + (q0 + r) * DK_ + c0 + q * 4);
            *(float4*)(Qs + r * LDA_ + c0 + q * 4) = v;
        }
    }

    float o[4][4];
    float mrow[4];
    float lrow[4];
#pragma unroll
    for (int i = 0; i < 4; i++) {
        mrow[i] = -INFINITY;
        lrow[i] = 0.0f;
#pragma unroll
        for (int j = 0; j < 4; j++)
            o[i][j] = 0.0f;
    }

    for (int kt = 0; kt <= qt; kt++) {
        __syncthreads();
        {
            int r  = tid >> 2;
            int c0 = (tid & 3) * 16;
            int kr = (kt * 64 + r) * DK_;
#pragma unroll
            for (int q = 0; q < 4; q++) {
                *(float4*)(Ks + r * LDA_ + c0 + q * 4) = *(const float4*)(Kb + kr + c0 + q * 4);
                *(float4*)(Vs + r * LDA_ + c0 + q * 4) = *(const float4*)(Vb + kr + c0 + q * 4);
            }
        }
        __syncthreads();

        float s[4][4];
#pragma unroll
        for (int i = 0; i < 4; i++)
#pragma unroll
            for (int j = 0; j < 4; j++)
                s[i][j] = 0.0f;

#pragma unroll
        for (int d4 = 0; d4 < 16; d4++) {
            float4 a[4];
            float4 bf[4];
#pragma unroll
            for (int i = 0; i < 4; i++)
                a[i]  = *(const float4*)(Qs + (ty * 4 + i) * LDA_ + d4 * 4);
#pragma unroll
            for (int j = 0; j < 4; j++)
                bf[j] = *(const float4*)(Ks + (tx * 4 + j) * LDA_ + d4 * 4);
#pragma unroll
            for (int i = 0; i < 4; i++) {
#pragma unroll
                for (int j = 0; j < 4; j++) {
                    s[i][j] = fmaf(a[i].x, bf[j].x, s[i][j]);
                    s[i][j] = fmaf(a[i].y, bf[j].y, s[i][j]);
                    s[i][j] = fmaf(a[i].z, bf[j].z, s[i][j]);
                    s[i][j] = fmaf(a[i].w, bf[j].w, s[i][j]);
                }
            }
        }

        const bool diag = (kt == qt);
#pragma unroll
        for (int i = 0; i < 4; i++) {
#pragma unroll
            for (int j = 0; j < 4; j++) {
                float v = s[i][j] * 0.125f;
                if (diag && (tx * 4 + j) > (ty * 4 + i))
                    v = -INFINITY;
                s[i][j] = v;
            }
        }

        float alpha[4];
#pragma unroll
        for (int i = 0; i < 4; i++) {
            float rm = fmaxf(fmaxf(s[i][0], s[i][1]), fmaxf(s[i][2], s[i][3]));
#pragma unroll
            for (int off = 1; off < 16; off <<= 1)
                rm = fmaxf(rm, __shfl_xor_sync(0xffffffffu, rm, off));
            float mnew = fmaxf(mrow[i], rm);
            float rs = 0.0f;
#pragma unroll
            for (int j = 0; j < 4; j++) {
                s[i][j] = __expf(s[i][j] - mnew);
                rs += s[i][j];
            }
#pragma unroll
            for (int off = 1; off < 16; off <<= 1)
                rs += __shfl_xor_sync(0xffffffffu, rs, off);
            alpha[i] = __expf(mrow[i] - mnew);
            lrow[i]  = lrow[i] * alpha[i] + rs;
            mrow[i]  = mnew;
        }
#pragma unroll
        for (int i = 0; i < 4; i++)
#pragma unroll
            for (int j = 0; j < 4; j++)
                o[i][j] *= alpha[i];

        __syncthreads();
#pragma unroll
        for (int j = 0; j < 4; j++)
#pragma unroll
            for (int i = 0; i < 4; i++)
                Ks[(tx * 4 + j) * LDA_ + (ty * 4 + i)] = s[i][j];
        __syncthreads();

#pragma unroll 8
        for (int c = 0; c < 64; c++) {
            float4 p  = *(const float4*)(Ks + c * LDA_ + ty * 4);
            float4 vv = *(const float4*)(Vs + c * LDA_ + tx * 4);
#pragma unroll
            for (int i = 0; i < 4; i++) {
                float pi = (i == 0) ? p.x : (i == 1) ? p.y : (i == 2) ? p.z : p.w;
                o[i][0] = fmaf(pi, vv.x, o[i][0]);
                o[i][1] = fmaf(pi, vv.y, o[i][1]);
                o[i][2] = fmaf(pi, vv.z, o[i][2]);
                o[i][3] = fmaf(pi, vv.w, o[i][3]);
            }
        }
    }

    const int bb = bh >> 4;
    const int hh = bh & 15;
#pragma unroll
    for (int i = 0; i < 4; i++) {
        float inv = 1.0f / lrow[i];
        int row = q0 + ty * 4 + i;
        float4 v;
        v.x = o[i][0] * inv;
        v.y = o[i][1] * inv;
        v.z = o[i][2] * inv;
        v.w = o[i][3] * inv;
        *(float4*)(g_o + ((size_t)bb * S_ + row) * D_ + hh * DK_ + tx * 4) = v;
    }
}

// ---------------------------------------------------------------------------
extern "C" void kernel_launch(void* const* d_in, const int* in_sizes, int n_in,
                              void* d_out, int out_size)
{
    const float* x  = (const float*)d_in[0];
    const float* Wq = (const float*)d_in[1];
    const float* bq = (const float*)d_in[2];
    const float* Wk = (const float*)d_in[3];
    const float* bk = (const float*)d_in[4];
    const float* Wv = (const float*)d_in[5];
    const float* bv = (const float*)d_in[6];
    const float* Wo = (const float*)d_in[7];
    const float* bo = (const float*)d_in[8];
    float* out = (float*)d_out;

    dim3 gg(D_ / 128, M_ / 128);   // (8, 64)
    gemm_q_kernel<<<gg, 256>>>(x, Wq, bq);
    gemm_k_kernel<<<gg, 256>>>(x, Wk, bk);
    gemm_v_kernel<<<gg, 256>>>(x, Wv, bv);

    const int smem = 3 * 64 * LDA_ * (int)sizeof(float);
    cudaFuncSetAttribute(attn_kernel, cudaFuncAttributeMaxDynamicSharedMemorySize, smem);
    attn_kernel<<<dim3(S_ / 64, B_ * H_), 256, smem>>>();

    gemm_o_kernel<<<gg, 256>>>(Wo, bo, out);
}

// round 4
// speedup vs baseline: 1.3161x; 1.0646x over previous
#include <cuda_runtime.h>
#include <cuda_bf16.h>
#include <cstdint>
#include <math.h>

#define B_  4
#define S_  2048
#define D_  1024
#define H_  16
#define DK_ 64
#define M_  (B_*S_)

// ---------------------------------------------------------------------------
// Scratch (__device__ globals; no allocations allowed)
// ---------------------------------------------------------------------------
__device__ float g_q[(size_t)M_*D_];   // [b,h,s,dk] fp32
__device__ float g_k[(size_t)M_*D_];
__device__ float g_v[(size_t)M_*D_];

__device__ __nv_bfloat16 g_xh[(size_t)M_*D_];   // input X split hi/lo
__device__ __nv_bfloat16 g_xl[(size_t)M_*D_];
__device__ __nv_bfloat16 g_oh[(size_t)M_*D_];   // attention out split hi/lo [b,s,h*64+d]
__device__ __nv_bfloat16 g_ol[(size_t)M_*D_];

__device__ __nv_bfloat16 g_wqh[(size_t)D_*D_], g_wql[(size_t)D_*D_];
__device__ __nv_bfloat16 g_wkh[(size_t)D_*D_], g_wkl[(size_t)D_*D_];
__device__ __nv_bfloat16 g_wvh[(size_t)D_*D_], g_wvl[(size_t)D_*D_];
__device__ __nv_bfloat16 g_woh[(size_t)D_*D_], g_wol[(size_t)D_*D_];

// ---------------------------------------------------------------------------
// Pack: fp32 -> bf16 hi + bf16 lo (residual)
// ---------------------------------------------------------------------------
__device__ __forceinline__ void pack_body(const float* __restrict__ src,
                                          __nv_bfloat16* __restrict__ hi,
                                          __nv_bfloat16* __restrict__ lo)
{
    int i = (blockIdx.x * 256 + threadIdx.x) * 4;
    float4 v = *(const float4*)(src + i);
    __nv_bfloat16 h0 = __float2bfloat16(v.x);
    __nv_bfloat16 h1 = __float2bfloat16(v.y);
    __nv_bfloat16 h2 = __float2bfloat16(v.z);
    __nv_bfloat16 h3 = __float2bfloat16(v.w);
    __nv_bfloat162 ph0; ph0.x = h0; ph0.y = h1;
    __nv_bfloat162 ph1; ph1.x = h2; ph1.y = h3;
    *(__nv_bfloat162*)(hi + i)     = ph0;
    *(__nv_bfloat162*)(hi + i + 2) = ph1;
    __nv_bfloat162 pl0;
    pl0.x = __float2bfloat16(v.x - __bfloat162float(h0));
    pl0.y = __float2bfloat16(v.y - __bfloat162float(h1));
    __nv_bfloat162 pl1;
    pl1.x = __float2bfloat16(v.z - __bfloat162float(h2));
    pl1.y = __float2bfloat16(v.w - __bfloat162float(h3));
    *(__nv_bfloat162*)(lo + i)     = pl0;
    *(__nv_bfloat162*)(lo + i + 2) = pl1;
}

__global__ __launch_bounds__(256) void pack_x_kernel (const float* __restrict__ s) { pack_body(s, g_xh, g_xl); }
__global__ __launch_bounds__(256) void pack_wq_kernel(const float* __restrict__ s) { pack_body(s, g_wqh, g_wql); }
__global__ __launch_bounds__(256) void pack_wk_kernel(const float* __restrict__ s) { pack_body(s, g_wkh, g_wkl); }
__global__ __launch_bounds__(256) void pack_wv_kernel(const float* __restrict__ s) { pack_body(s, g_wvh, g_wvl); }
__global__ __launch_bounds__(256) void pack_wo_kernel(const float* __restrict__ s) { pack_body(s, g_woh, g_wol); }

// ---------------------------------------------------------------------------
// Tensor-core GEMM, bf16 split 3-pass: Y = X @ W^T + bias
// A/B already split to bf16 hi/lo in gmem; cp.async double-buffered staging.
// ---------------------------------------------------------------------------

__device__ __forceinline__ void ldsm4(uint32_t* r, uint32_t addr)
{
    asm volatile("ldmatrix.sync.aligned.m8n8.x4.shared.b16 {%0,%1,%2,%3}, [%4];"
        : "=r"(r[0]), "=r"(r[1]), "=r"(r[2]), "=r"(r[3]) : "r"(addr));
}

__device__ __forceinline__ void mma16816(float* c, const uint32_t* a, const uint32_t* b)
{
    asm volatile("mma.sync.aligned.m16n8k16.row.col.f32.bf16.bf16.f32 "
        "{%0,%1,%2,%3}, {%4,%5,%6,%7}, {%8,%9}, {%0,%1,%2,%3};"
        : "+f"(c[0]), "+f"(c[1]), "+f"(c[2]), "+f"(c[3])
        : "r"(a[0]), "r"(a[1]), "r"(a[2]), "r"(a[3]), "r"(b[0]), "r"(b[1]));
}

__device__ __forceinline__ void cpasync16(uint32_t dst, const void* src)
{
    asm volatile("cp.async.cg.shared.global [%0], [%1], 16;" :: "r"(dst), "l"(src));
}

#define GLDA 40                     // 32 + 8 halves pad (80B rows, 16B aligned)
#define GT   (128 * GLDA)           // halves per tile
#define GSM  (2 * 4 * GT * 2)       // dynamic smem bytes: 2 stages x 4 tiles

template<int MODE>
__device__ __forceinline__ void gemm_tc(const __nv_bfloat16* __restrict__ Xh,
                                        const __nv_bfloat16* __restrict__ Xl,
                                        const __nv_bfloat16* __restrict__ Wh,
                                        const __nv_bfloat16* __restrict__ Wl,
                                        const float* __restrict__ bias,
                                        float* __restrict__ Y)
{
    extern __shared__ __nv_bfloat16 smem[];

    const int tid  = threadIdx.x;           // 256
    const int lane = tid & 31;
    const int w    = tid >> 5;
    const int wm   = (w >> 2) * 64;
    const int wn   = (w & 3) * 32;
    const int row0 = blockIdx.y * 128;
    const int col0 = blockIdx.x * 128;

    float acc[4][4][4];
#pragma unroll
    for (int im = 0; im < 4; im++)
#pragma unroll
        for (int in = 0; in < 4; in++)
#pragma unroll
            for (int q = 0; q < 4; q++)
                acc[im][in][q] = 0.0f;

    const uint32_t aS = (uint32_t)__cvta_generic_to_shared(smem);

    // copy mapping: r = tid>>2 in [0,64), c8 = (tid&3)*8 halves; rows r and r+64
    const int cr  = tid >> 2;
    const int cc8 = (tid & 3) * 8;

    const __nv_bfloat16* srcA_h = Xh + (size_t)(row0 + cr) * D_ + cc8;
    const __nv_bfloat16* srcA_l = Xl + (size_t)(row0 + cr) * D_ + cc8;
    const __nv_bfloat16* srcB_h = Wh + (size_t)(col0 + cr) * D_ + cc8;
    const __nv_bfloat16* srcB_l = Wl + (size_t)(col0 + cr) * D_ + cc8;
    const uint32_t dOff = (uint32_t)(cr * GLDA + cc8) * 2;
    const uint32_t dRow64 = (uint32_t)(64 * GLDA) * 2;

#define ISSUE_COPY(sstage, k0v)                                                   \
    do {                                                                          \
        uint32_t db = aS + (uint32_t)((sstage) * 4 * GT) * 2 + dOff;              \
        cpasync16(db,                        srcA_h + (k0v));                     \
        cpasync16(db + dRow64,               srcA_h + (k0v) + 64 * D_);           \
        cpasync16(db + (uint32_t)GT*2,       srcA_l + (k0v));                     \
        cpasync16(db + (uint32_t)GT*2 + dRow64, srcA_l + (k0v) + 64 * D_);        \
        cpasync16(db + (uint32_t)GT*4,       srcB_h + (k0v));                     \
        cpasync16(db + (uint32_t)GT*4 + dRow64, srcB_h + (k0v) + 64 * D_);        \
        cpasync16(db + (uint32_t)GT*6,       srcB_l + (k0v));                     \
        cpasync16(db + (uint32_t)GT*6 + dRow64, srcB_l + (k0v) + 64 * D_);        \
        asm volatile("cp.async.commit_group;");                                   \
    } while (0)

    ISSUE_COPY(0, 0);

    for (int kt = 0; kt < D_ / 32; kt++) {
        const int s = kt & 1;
        asm volatile("cp.async.wait_group 0;");
        __syncthreads();
        if (kt + 1 < D_ / 32)
            ISSUE_COPY(s ^ 1, (kt + 1) * 32);

        const uint32_t bAh = aS + (uint32_t)((s * 4 + 0) * GT) * 2;
        const uint32_t bAl = aS + (uint32_t)((s * 4 + 1) * GT) * 2;
        const uint32_t bBh = aS + (uint32_t)((s * 4 + 2) * GT) * 2;
        const uint32_t bBl = aS + (uint32_t)((s * 4 + 3) * GT) * 2;

#pragma unroll
        for (int kc = 0; kc < 2; kc++) {
            const uint32_t colb = (uint32_t)(kc * 16 + ((lane >> 4) << 3)) * 2;
            uint32_t afh[4][4];
            uint32_t afl[4][4];
#pragma unroll
            for (int im = 0; im < 4; im++) {
                uint32_t off = (uint32_t)((wm + im * 16 + (lane & 15)) * GLDA) * 2 + colb;
                ldsm4(afh[im], bAh + off);
                ldsm4(afl[im], bAl + off);
            }
            uint32_t bfh[4][2];
            uint32_t bfl[4][2];
#pragma unroll
            for (int np = 0; np < 2; np++) {
                uint32_t off = (uint32_t)((wn + np * 16 + (lane & 15)) * GLDA) * 2 + colb;
                uint32_t r4[4];
                ldsm4(r4, bBh + off);
                bfh[np * 2 + 0][0] = r4[0];
                bfh[np * 2 + 0][1] = r4[2];
                bfh[np * 2 + 1][0] = r4[1];
                bfh[np * 2 + 1][1] = r4[3];
                ldsm4(r4, bBl + off);
                bfl[np * 2 + 0][0] = r4[0];
                bfl[np * 2 + 0][1] = r4[2];
                bfl[np * 2 + 1][0] = r4[1];
                bfl[np * 2 + 1][1] = r4[3];
            }
#pragma unroll
            for (int im = 0; im < 4; im++) {
#pragma unroll
                for (int in = 0; in < 4; in++) {
                    mma16816(acc[im][in], afh[im], bfh[in]);
                    mma16816(acc[im][in], afh[im], bfl[in]);
                    mma16816(acc[im][in], afl[im], bfh[in]);
                }
            }
        }
        __syncthreads();
    }
#undef ISSUE_COPY

    const int r_in = lane >> 2;
    const int c_in = (lane & 3) * 2;
#pragma unroll
    for (int im = 0; im < 4; im++) {
#pragma unroll
        for (int in = 0; in < 4; in++) {
            int rg = row0 + wm + im * 16 + r_in;
            int cg = col0 + wn + in * 8 + c_in;
            float b0 = bias[cg];
            float b1 = bias[cg + 1];
            float2 v0;
            float2 v1;
            v0.x = acc[im][in][0] + b0;
            v0.y = acc[im][in][1] + b1;
            v1.x = acc[im][in][2] + b0;
            v1.y = acc[im][in][3] + b1;
            if (MODE == 0) {
                *(float2*)(Y + (size_t)rg * D_ + cg)       = v0;
                *(float2*)(Y + (size_t)(rg + 8) * D_ + cg) = v1;
            } else {
                int hh = cg >> 6;
                int dd = cg & 63;
                int bb = rg >> 11;
                int ss = rg & (S_ - 1);
                size_t base = (((size_t)bb * H_ + hh) * S_ + ss) * DK_ + dd;
                *(float2*)(Y + base)           = v0;
                *(float2*)(Y + base + 8 * DK_) = v1;
            }
        }
    }
}

__global__ __launch_bounds__(256) void gemm_q_kernel(const float* __restrict__ b)
{ gemm_tc<1>(g_xh, g_xl, g_wqh, g_wql, b, g_q); }
__global__ __launch_bounds__(256) void gemm_k_kernel(const float* __restrict__ b)
{ gemm_tc<1>(g_xh, g_xl, g_wkh, g_wkl, b, g_k); }
__global__ __launch_bounds__(256) void gemm_v_kernel(const float* __restrict__ b)
{ gemm_tc<1>(g_xh, g_xl, g_wvh, g_wvl, b, g_v); }
__global__ __launch_bounds__(256) void gemm_o_kernel(const float* __restrict__ b,
                                                     float* __restrict__ out)
{ gemm_tc<0>(g_oh, g_ol, g_woh, g_wol, b, out); }

// ---------------------------------------------------------------------------
// Flash attention (fp32) — round-1 core; epilogue now writes bf16 hi/lo.
// ---------------------------------------------------------------------------
#define LDA_ 68

__global__ __launch_bounds__(256) void attn_kernel()
{
    extern __shared__ float sm[];
    float* Qs = sm;
    float* Ks = sm + 64 * LDA_;
    float* Vs = sm + 2 * 64 * LDA_;

    const int tid = threadIdx.x;
    const int tx  = tid & 15;
    const int ty  = tid >> 4;
    const int bh  = blockIdx.y;
    const int qt  = blockIdx.x;
    const int q0  = qt * 64;

    const float* Qb = g_q + (size_t)bh * S_ * DK_;
    const float* Kb = g_k + (size_t)bh * S_ * DK_;
    const float* Vb = g_v + (size_t)bh * S_ * DK_;

    {
        int r  = tid >> 2;
        int c0 = (tid & 3) * 16;
#pragma unroll
        for (int q = 0; q < 4; q++) {
            float4 v = *(const float4*)(Qb + (q0 + r) * DK_ + c0 + q * 4);
            *(float4*)(Qs + r * LDA_ + c0 + q * 4) = v;
        }
    }

    float o[4][4];
    float mrow[4];
    float lrow[4];
#pragma unroll
    for (int i = 0; i < 4; i++) {
        mrow[i] = -INFINITY;
        lrow[i] = 0.0f;
#pragma unroll
        for (int j = 0; j < 4; j++)
            o[i][j] = 0.0f;
    }

    for (int kt = 0; kt <= qt; kt++) {
        __syncthreads();
        {
            int r  = tid >> 2;
            int c0 = (tid & 3) * 16;
            int kr = (kt * 64 + r) * DK_;
#pragma unroll
            for (int q = 0; q < 4; q++) {
                *(float4*)(Ks + r * LDA_ + c0 + q * 4) = *(const float4*)(Kb + kr + c0 + q * 4);
                *(float4*)(Vs + r * LDA_ + c0 + q * 4) = *(const float4*)(Vb + kr + c0 + q * 4);
            }
        }
        __syncthreads();

        float s[4][4];
#pragma unroll
        for (int i = 0; i < 4; i++)
#pragma unroll
            for (int j = 0; j < 4; j++)
                s[i][j] = 0.0f;

#pragma unroll
        for (int d4 = 0; d4 < 16; d4++) {
            float4 a[4];
            float4 bf[4];
#pragma unroll
            for (int i = 0; i < 4; i++)
                a[i]  = *(const float4*)(Qs + (ty * 4 + i) * LDA_ + d4 * 4);
#pragma unroll
            for (int j = 0; j < 4; j++)
                bf[j] = *(const float4*)(Ks + (tx * 4 + j) * LDA_ + d4 * 4);
#pragma unroll
            for (int i = 0; i < 4; i++) {
#pragma unroll
                for (int j = 0; j < 4; j++) {
                    s[i][j] = fmaf(a[i].x, bf[j].x, s[i][j]);
                    s[i][j] = fmaf(a[i].y, bf[j].y, s[i][j]);
                    s[i][j] = fmaf(a[i].z, bf[j].z, s[i][j]);
                    s[i][j] = fmaf(a[i].w, bf[j].w, s[i][j]);
                }
            }
        }

        const bool diag = (kt == qt);
#pragma unroll
        for (int i = 0; i < 4; i++) {
#pragma unroll
            for (int j = 0; j < 4; j++) {
                float v = s[i][j] * 0.125f;
                if (diag && (tx * 4 + j) > (ty * 4 + i))
                    v = -INFINITY;
                s[i][j] = v;
            }
        }

        float alpha[4];
#pragma unroll
        for (int i = 0; i < 4; i++) {
            float rm = fmaxf(fmaxf(s[i][0], s[i][1]), fmaxf(s[i][2], s[i][3]));
#pragma unroll
            for (int off = 1; off < 16; off <<= 1)
                rm = fmaxf(rm, __shfl_xor_sync(0xffffffffu, rm, off));
            float mnew = fmaxf(mrow[i], rm);
            float rs = 0.0f;
#pragma unroll
            for (int j = 0; j < 4; j++) {
                s[i][j] = __expf(s[i][j] - mnew);
                rs += s[i][j];
            }
#pragma unroll
            for (int off = 1; off < 16; off <<= 1)
                rs += __shfl_xor_sync(0xffffffffu, rs, off);
            alpha[i] = __expf(mrow[i] - mnew);
            lrow[i]  = lrow[i] * alpha[i] + rs;
            mrow[i]  = mnew;
        }
#pragma unroll
        for (int i = 0; i < 4; i++)
#pragma unroll
            for (int j = 0; j < 4; j++)
                o[i][j] *= alpha[i];

        __syncthreads();
#pragma unroll
        for (int j = 0; j < 4; j++)
#pragma unroll
            for (int i = 0; i < 4; i++)
                Ks[(tx * 4 + j) * LDA_ + (ty * 4 + i)] = s[i][j];
        __syncthreads();

#pragma unroll 8
        for (int c = 0; c < 64; c++) {
            float4 p  = *(const float4*)(Ks + c * LDA_ + ty * 4);
            float4 vv = *(const float4*)(Vs + c * LDA_ + tx * 4);
#pragma unroll
            for (int i = 0; i < 4; i++) {
                float pi = (i == 0) ? p.x : (i == 1) ? p.y : (i == 2) ? p.z : p.w;
                o[i][0] = fmaf(pi, vv.x, o[i][0]);
                o[i][1] = fmaf(pi, vv.y, o[i][1]);
                o[i][2] = fmaf(pi, vv.z, o[i][2]);
                o[i][3] = fmaf(pi, vv.w, o[i][3]);
            }
        }
    }

    const int bb = bh >> 4;
    const int hh = bh & 15;
#pragma unroll
    for (int i = 0; i < 4; i++) {
        float inv = 1.0f / lrow[i];
        int row = q0 + ty * 4 + i;
        float v0 = o[i][0] * inv;
        float v1 = o[i][1] * inv;
        float v2 = o[i][2] * inv;
        float v3 = o[i][3] * inv;
        size_t idx = ((size_t)bb * S_ + row) * D_ + hh * DK_ + tx * 4;
        __nv_bfloat16 h0 = __float2bfloat16(v0);
        __nv_bfloat16 h1 = __float2bfloat16(v1);
        __nv_bfloat16 h2 = __float2bfloat16(v2);
        __nv_bfloat16 h3 = __float2bfloat16(v3);
        __nv_bfloat162 ph0; ph0.x = h0; ph0.y = h1;
        __nv_bfloat162 ph1; ph1.x = h2; ph1.y = h3;
        *(__nv_bfloat162*)(g_oh + idx)     = ph0;
        *(__nv_bfloat162*)(g_oh + idx + 2) = ph1;
        __nv_bfloat162 pl0;
        pl0.x = __float2bfloat16(v0 - __bfloat162float(h0));
        pl0.y = __float2bfloat16(v1 - __bfloat162float(h1));
        __nv_bfloat162 pl1;
        pl1.x = __float2bfloat16(v2 - __bfloat162float(h2));
        pl1.y = __float2bfloat16(v3 - __bfloat162float(h3));
        *(__nv_bfloat162*)(g_ol + idx)     = pl0;
        *(__nv_bfloat162*)(g_ol + idx + 2) = pl1;
    }
}

// ---------------------------------------------------------------------------
extern "C" void kernel_launch(void* const* d_in, const int* in_sizes, int n_in,
                              void* d_out, int out_size)
{
    const float* x  = (const float*)d_in[0];
    const float* Wq = (const float*)d_in[1];
    const float* bq = (const float*)d_in[2];
    const float* Wk = (const float*)d_in[3];
    const float* bk = (const float*)d_in[4];
    const float* Wv = (const float*)d_in[5];
    const float* bv = (const float*)d_in[6];
    const float* Wo = (const float*)d_in[7];
    const float* bo = (const float*)d_in[8];
    float* out = (float*)d_out;

    pack_x_kernel <<<(M_ * D_) / 1024, 256>>>(x);
    pack_wq_kernel<<<(D_ * D_) / 1024, 256>>>(Wq);
    pack_wk_kernel<<<(D_ * D_) / 1024, 256>>>(Wk);
    pack_wv_kernel<<<(D_ * D_) / 1024, 256>>>(Wv);
    pack_wo_kernel<<<(D_ * D_) / 1024, 256>>>(Wo);

    static int attr_set = 0;
    if (!attr_set) {
        cudaFuncSetAttribute(gemm_q_kernel, cudaFuncAttributeMaxDynamicSharedMemorySize, GSM);
        cudaFuncSetAttribute(gemm_k_kernel, cudaFuncAttributeMaxDynamicSharedMemorySize, GSM);
        cudaFuncSetAttribute(gemm_v_kernel, cudaFuncAttributeMaxDynamicSharedMemorySize, GSM);
        cudaFuncSetAttribute(gemm_o_kernel, cudaFuncAttributeMaxDynamicSharedMemorySize, GSM);
        cudaFuncSetAttribute(attn_kernel,   cudaFuncAttributeMaxDynamicSharedMemorySize,
                             3 * 64 * LDA_ * (int)sizeof(float));
        attr_set = 1;
    }

    dim3 gg(D_ / 128, M_ / 128);   // (8, 64)
    gemm_q_kernel<<<gg, 256, GSM>>>(bq);
    gemm_k_kernel<<<gg, 256, GSM>>>(bk);
    gemm_v_kernel<<<gg, 256, GSM>>>(bv);

    attn_kernel<<<dim3(S_ / 64, B_ * H_), 256, 3 * 64 * LDA_ * (int)sizeof(float)>>>();

    gemm_o_kernel<<<gg, 256, GSM>>>(bo, out);
}

// round 5
// speedup vs baseline: 2.6303x; 1.9985x over previous
#include <cuda_runtime.h>
#include <cuda_bf16.h>
#include <cstdint>
#include <math.h>

#define B_  4
#define S_  2048
#define D_  1024
#define H_  16
#define DK_ 64
#define M_  (B_*S_)

// ---------------------------------------------------------------------------
// Scratch (__device__ globals; no allocations allowed). All operand tensors
// live as split bf16 (hi + lo residual): value = hi + lo, ~16 mantissa bits.
// ---------------------------------------------------------------------------
__device__ __nv_bfloat16 g_xh[(size_t)M_*D_];   // input X
__device__ __nv_bfloat16 g_xl[(size_t)M_*D_];
__device__ __nv_bfloat16 g_qh[(size_t)M_*D_];   // Q  [b,h,s,dk]
__device__ __nv_bfloat16 g_ql[(size_t)M_*D_];
__device__ __nv_bfloat16 g_kh[(size_t)M_*D_];   // K  [b,h,s,dk]
__device__ __nv_bfloat16 g_kl[(size_t)M_*D_];
__device__ __nv_bfloat16 g_vh[(size_t)M_*D_];   // V  [b,h,s,dk]
__device__ __nv_bfloat16 g_vl[(size_t)M_*D_];
__device__ __nv_bfloat16 g_oh[(size_t)M_*D_];   // attn out [b,s,h*64+d]
__device__ __nv_bfloat16 g_ol[(size_t)M_*D_];

__device__ __nv_bfloat16 g_wqh[(size_t)D_*D_], g_wql[(size_t)D_*D_];
__device__ __nv_bfloat16 g_wkh[(size_t)D_*D_], g_wkl[(size_t)D_*D_];
__device__ __nv_bfloat16 g_wvh[(size_t)D_*D_], g_wvl[(size_t)D_*D_];
__device__ __nv_bfloat16 g_woh[(size_t)D_*D_], g_wol[(size_t)D_*D_];

// ---------------------------------------------------------------------------
// helpers
// ---------------------------------------------------------------------------
__device__ __forceinline__ void split2(float a, float b,
                                       __nv_bfloat162& h2, __nv_bfloat162& l2)
{
    h2.x = __float2bfloat16(a);
    h2.y = __float2bfloat16(b);
    l2.x = __float2bfloat16(a - __bfloat162float(h2.x));
    l2.y = __float2bfloat16(b - __bfloat162float(h2.y));
}

__device__ __forceinline__ void split_pack(float a, float b, uint32_t& hi, uint32_t& lo)
{
    __nv_bfloat162 h2, l2;
    split2(a, b, h2, l2);
    hi = *(uint32_t*)&h2;
    lo = *(uint32_t*)&l2;
}

__device__ __forceinline__ void ldsm4(uint32_t* r, uint32_t addr)
{
    asm volatile("ldmatrix.sync.aligned.m8n8.x4.shared.b16 {%0,%1,%2,%3}, [%4];"
        : "=r"(r[0]), "=r"(r[1]), "=r"(r[2]), "=r"(r[3]) : "r"(addr));
}

__device__ __forceinline__ void ldsm4t(uint32_t* r, uint32_t addr)
{
    asm volatile("ldmatrix.sync.aligned.m8n8.x4.trans.shared.b16 {%0,%1,%2,%3}, [%4];"
        : "=r"(r[0]), "=r"(r[1]), "=r"(r[2]), "=r"(r[3]) : "r"(addr));
}

__device__ __forceinline__ void mma16816(float* c, const uint32_t* a, const uint32_t* b)
{
    asm volatile("mma.sync.aligned.m16n8k16.row.col.f32.bf16.bf16.f32 "
        "{%0,%1,%2,%3}, {%4,%5,%6,%7}, {%8,%9}, {%0,%1,%2,%3};"
        : "+f"(c[0]), "+f"(c[1]), "+f"(c[2]), "+f"(c[3])
        : "r"(a[0]), "r"(a[1]), "r"(a[2]), "r"(a[3]), "r"(b[0]), "r"(b[1]));
}

__device__ __forceinline__ void cpasync16(uint32_t dst, const void* src)
{
    asm volatile("cp.async.cg.shared.global [%0], [%1], 16;" :: "r"(dst), "l"(src));
}

// ---------------------------------------------------------------------------
// Pack: fp32 -> bf16 hi + lo
// ---------------------------------------------------------------------------
__device__ __forceinline__ void pack_body(const float* __restrict__ src,
                                          __nv_bfloat16* __restrict__ hi,
                                          __nv_bfloat16* __restrict__ lo)
{
    int i = (blockIdx.x * 256 + threadIdx.x) * 4;
    float4 v = *(const float4*)(src + i);
    __nv_bfloat162 h0, l0, h1, l1;
    split2(v.x, v.y, h0, l0);
    split2(v.z, v.w, h1, l1);
    *(__nv_bfloat162*)(hi + i)     = h0;
    *(__nv_bfloat162*)(hi + i + 2) = h1;
    *(__nv_bfloat162*)(lo + i)     = l0;
    *(__nv_bfloat162*)(lo + i + 2) = l1;
}

__global__ __launch_bounds__(256) void pack_x_kernel (const float* __restrict__ s) { pack_body(s, g_xh, g_xl); }
__global__ __launch_bounds__(256) void pack_wq_kernel(const float* __restrict__ s) { pack_body(s, g_wqh, g_wql); }
__global__ __launch_bounds__(256) void pack_wk_kernel(const float* __restrict__ s) { pack_body(s, g_wkh, g_wkl); }
__global__ __launch_bounds__(256) void pack_wv_kernel(const float* __restrict__ s) { pack_body(s, g_wvh, g_wvl); }
__global__ __launch_bounds__(256) void pack_wo_kernel(const float* __restrict__ s) { pack_body(s, g_woh, g_wol); }

// ---------------------------------------------------------------------------
// Tensor-core GEMM (split bf16, 3-pass), cp.async double-buffered.
// MODE 0: fp32 row-major out.  MODE 1: bf16 hi/lo out in head layout.
// ---------------------------------------------------------------------------
#define GLDA 40
#define GT   (128 * GLDA)
#define GSM  (2 * 4 * GT * 2)

template<int MODE>
__device__ __forceinline__ void gemm_tc(const __nv_bfloat16* __restrict__ Xh,
                                        const __nv_bfloat16* __restrict__ Xl,
                                        const __nv_bfloat16* __restrict__ Wh,
                                        const __nv_bfloat16* __restrict__ Wl,
                                        const float* __restrict__ bias,
                                        float* __restrict__ Yf,
                                        __nv_bfloat16* __restrict__ Yh,
                                        __nv_bfloat16* __restrict__ Yl)
{
    extern __shared__ __nv_bfloat16 smem[];

    const int tid  = threadIdx.x;
    const int lane = tid & 31;
    const int w    = tid >> 5;
    const int wm   = (w >> 2) * 64;
    const int wn   = (w & 3) * 32;
    const int row0 = blockIdx.y * 128;
    const int col0 = blockIdx.x * 128;

    float acc[4][4][4];
#pragma unroll
    for (int im = 0; im < 4; im++)
#pragma unroll
        for (int in = 0; in < 4; in++)
#pragma unroll
            for (int q = 0; q < 4; q++)
                acc[im][in][q] = 0.0f;

    const uint32_t aS = (uint32_t)__cvta_generic_to_shared(smem);
    const int cr  = tid >> 2;
    const int cc8 = (tid & 3) * 8;

    const __nv_bfloat16* srcA_h = Xh + (size_t)(row0 + cr) * D_ + cc8;
    const __nv_bfloat16* srcA_l = Xl + (size_t)(row0 + cr) * D_ + cc8;
    const __nv_bfloat16* srcB_h = Wh + (size_t)(col0 + cr) * D_ + cc8;
    const __nv_bfloat16* srcB_l = Wl + (size_t)(col0 + cr) * D_ + cc8;
    const uint32_t dOff   = (uint32_t)(cr * GLDA + cc8) * 2;
    const uint32_t dRow64 = (uint32_t)(64 * GLDA) * 2;

#define ISSUE_COPY(sstage, k0v)                                                   \
    do {                                                                          \
        uint32_t db = aS + (uint32_t)((sstage) * 4 * GT) * 2 + dOff;              \
        cpasync16(db,                           srcA_h + (k0v));                  \
        cpasync16(db + dRow64,                  srcA_h + (k0v) + 64 * D_);        \
        cpasync16(db + (uint32_t)GT*2,          srcA_l + (k0v));                  \
        cpasync16(db + (uint32_t)GT*2 + dRow64, srcA_l + (k0v) + 64 * D_);        \
        cpasync16(db + (uint32_t)GT*4,          srcB_h + (k0v));                  \
        cpasync16(db + (uint32_t)GT*4 + dRow64, srcB_h + (k0v) + 64 * D_);        \
        cpasync16(db + (uint32_t)GT*6,          srcB_l + (k0v));                  \
        cpasync16(db + (uint32_t)GT*6 + dRow64, srcB_l + (k0v) + 64 * D_);        \
        asm volatile("cp.async.commit_group;");                                   \
    } while (0)

    ISSUE_COPY(0, 0);

    for (int kt = 0; kt < D_ / 32; kt++) {
        const int s = kt & 1;
        asm volatile("cp.async.wait_group 0;");
        __syncthreads();
        if (kt + 1 < D_ / 32)
            ISSUE_COPY(s ^ 1, (kt + 1) * 32);

        const uint32_t bAh = aS + (uint32_t)((s * 4 + 0) * GT) * 2;
        const uint32_t bAl = aS + (uint32_t)((s * 4 + 1) * GT) * 2;
        const uint32_t bBh = aS + (uint32_t)((s * 4 + 2) * GT) * 2;
        const uint32_t bBl = aS + (uint32_t)((s * 4 + 3) * GT) * 2;

#pragma unroll
        for (int kc = 0; kc < 2; kc++) {
            const uint32_t colb = (uint32_t)(kc * 16 + ((lane >> 4) << 3)) * 2;
            uint32_t afh[4][4];
            uint32_t afl[4][4];
#pragma unroll
            for (int im = 0; im < 4; im++) {
                uint32_t off = (uint32_t)((wm + im * 16 + (lane & 15)) * GLDA) * 2 + colb;
                ldsm4(afh[im], bAh + off);
                ldsm4(afl[im], bAl + off);
            }
            uint32_t bfh[4][2];
            uint32_t bfl[4][2];
#pragma unroll
            for (int np = 0; np < 2; np++) {
                uint32_t off = (uint32_t)((wn + np * 16 + (lane & 15)) * GLDA) * 2 + colb;
                uint32_t r4[4];
                ldsm4(r4, bBh + off);
                bfh[np * 2 + 0][0] = r4[0];
                bfh[np * 2 + 0][1] = r4[2];
                bfh[np * 2 + 1][0] = r4[1];
                bfh[np * 2 + 1][1] = r4[3];
                ldsm4(r4, bBl + off);
                bfl[np * 2 + 0][0] = r4[0];
                bfl[np * 2 + 0][1] = r4[2];
                bfl[np * 2 + 1][0] = r4[1];
                bfl[np * 2 + 1][1] = r4[3];
            }
#pragma unroll
            for (int im = 0; im < 4; im++) {
#pragma unroll
                for (int in = 0; in < 4; in++) {
                    mma16816(acc[im][in], afh[im], bfh[in]);
                    mma16816(acc[im][in], afh[im], bfl[in]);
                    mma16816(acc[im][in], afl[im], bfh[in]);
                }
            }
        }
        __syncthreads();
    }
#undef ISSUE_COPY

    const int r_in = lane >> 2;
    const int c_in = (lane & 3) * 2;
#pragma unroll
    for (int im = 0; im < 4; im++) {
#pragma unroll
        for (int in = 0; in < 4; in++) {
            int rg = row0 + wm + im * 16 + r_in;
            int cg = col0 + wn + in * 8 + c_in;
            float b0 = bias[cg];
            float b1 = bias[cg + 1];
            float2 v0;
            float2 v1;
            v0.x = acc[im][in][0] + b0;
            v0.y = acc[im][in][1] + b1;
            v1.x = acc[im][in][2] + b0;
            v1.y = acc[im][in][3] + b1;
            if (MODE == 0) {
                *(float2*)(Yf + (size_t)rg * D_ + cg)       = v0;
                *(float2*)(Yf + (size_t)(rg + 8) * D_ + cg) = v1;
            } else {
                int hh = cg >> 6;
                int dd = cg & 63;
                int bb = rg >> 11;
                int ss = rg & (S_ - 1);
                size_t base = (((size_t)bb * H_ + hh) * S_ + ss) * DK_ + dd;
                __nv_bfloat162 h2, l2;
                split2(v0.x, v0.y, h2, l2);
                *(__nv_bfloat162*)(Yh + base) = h2;
                *(__nv_bfloat162*)(Yl + base) = l2;
                split2(v1.x, v1.y, h2, l2);
                *(__nv_bfloat162*)(Yh + base + 8 * DK_) = h2;
                *(__nv_bfloat162*)(Yl + base + 8 * DK_) = l2;
            }
        }
    }
}

__global__ __launch_bounds__(256) void gemm_q_kernel(const float* __restrict__ b)
{ gemm_tc<1>(g_xh, g_xl, g_wqh, g_wql, b, nullptr, g_qh, g_ql); }
__global__ __launch_bounds__(256) void gemm_k_kernel(const float* __restrict__ b)
{ gemm_tc<1>(g_xh, g_xl, g_wkh, g_wkl, b, nullptr, g_kh, g_kl); }
__global__ __launch_bounds__(256) void gemm_v_kernel(const float* __restrict__ b)
{ gemm_tc<1>(g_xh, g_xl, g_wvh, g_wvl, b, nullptr, g_vh, g_vl); }
__global__ __launch_bounds__(256) void gemm_o_kernel(const float* __restrict__ b,
                                                     float* __restrict__ out)
{ gemm_tc<0>(g_oh, g_ol, g_woh, g_wol, b, out, nullptr, nullptr); }

// ---------------------------------------------------------------------------
// Tensor-core flash attention, split bf16 3-pass.
// Block: 256 threads (8 warps), Q tile 128 rows (16 per warp), KV tiles 64.
// smem (halves): Qh[128*72] Ql[128*72] | stage{0,1}: Kh Kl Vh Vl [64*72] each
// ---------------------------------------------------------------------------
#define LDQ   72
#define AQH   0
#define AQL   (128*LDQ)
#define AKV0  (2*128*LDQ)
#define KVARR (64*LDQ)          // 4608 halves per array
#define KVST  (4*KVARR)         // per-stage halves
#define ASM_BYTES ((AKV0 + 2*KVST) * 2)

__global__ __launch_bounds__(256) void attn_kernel()
{
    extern __shared__ __nv_bfloat16 sm[];
    const int tid  = threadIdx.x;
    const int lane = tid & 31;
    const int w    = tid >> 5;
    const int bh   = blockIdx.y;
    const int qt   = blockIdx.x;
    const int q0   = qt * 128;
    const int wrow = w * 16;

    const size_t hb = (size_t)bh * S_ * DK_;
    const uint32_t aS = (uint32_t)__cvta_generic_to_shared(sm);

    // Q prologue copy (hi+lo): 2 arrays x 128 rows, one row per thread
    {
        int a = tid >> 7;
        int r = tid & 127;
        const __nv_bfloat16* src = (a ? g_ql : g_qh) + hb + (size_t)(q0 + r) * DK_;
        uint32_t dst = aS + (uint32_t)((a ? AQL : AQH) + r * LDQ) * 2;
#pragma unroll
        for (int c = 0; c < 8; c++)
            cpasync16(dst + c * 16, src + c * 8);
    }

    const int kv_a = tid >> 6;           // 0:Kh 1:Kl 2:Vh 3:Vl
    const int kv_r = tid & 63;
    const __nv_bfloat16* kv_src =
        ((kv_a == 0) ? g_kh : (kv_a == 1) ? g_kl : (kv_a == 2) ? g_vh : g_vl)
        + hb + (size_t)kv_r * DK_;
    const uint32_t kv_doff = (uint32_t)(AKV0 + kv_a * KVARR + kv_r * LDQ) * 2;

#define ISSUE_KV(kt_, st_)                                                        \
    do {                                                                          \
        const __nv_bfloat16* sp = kv_src + (size_t)(kt_) * 64 * DK_;              \
        uint32_t dst = aS + kv_doff + (uint32_t)((st_) * KVST) * 2;               \
        _Pragma("unroll")                                                         \
        for (int c = 0; c < 8; c++)                                               \
            cpasync16(dst + c * 16, sp + c * 8);                                  \
        asm volatile("cp.async.commit_group;");                                   \
    } while (0)

    ISSUE_KV(0, 0);

    const int ktmax = 2 * qt + 1;

    float o[8][4];
#pragma unroll
    for (int j = 0; j < 8; j++)
#pragma unroll
        for (int q = 0; q < 4; q++)
            o[j][q] = 0.0f;
    float m0 = -INFINITY, m1 = -INFINITY, l0 = 0.0f, l1 = 0.0f;

    uint32_t qfh[4][4];
    uint32_t qfl[4][4];

    for (int kt = 0; kt <= ktmax; kt++) {
        const int st = kt & 1;
        asm volatile("cp.async.wait_group 0;");
        __syncthreads();
        if (kt < ktmax)
            ISSUE_KV(kt + 1, st ^ 1);

        if (kt == 0) {
#pragma unroll
            for (int t = 0; t < 4; t++) {
                uint32_t off = (uint32_t)((wrow + (lane & 15)) * LDQ
                                          + t * 16 + ((lane >> 4) << 3)) * 2;
                ldsm4(qfh[t], aS + (uint32_t)AQH * 2 + off);
                ldsm4(qfl[t], aS + (uint32_t)AQL * 2 + off);
            }
        }

        if (kt * 64 <= q0 + wrow + 15) {     // warp has unmasked rows in this tile
            const uint32_t kvb = aS + (uint32_t)(AKV0 + st * KVST) * 2;

            // ---- S = Q K^T ----
            float sf[8][4];
#pragma unroll
            for (int j = 0; j < 8; j++)
#pragma unroll
                for (int q = 0; q < 4; q++)
                    sf[j][q] = 0.0f;

#pragma unroll
            for (int t = 0; t < 4; t++) {
                const uint32_t colb = (uint32_t)(t * 16 + ((lane >> 4) << 3)) * 2;
#pragma unroll
                for (int nt = 0; nt < 4; nt++) {
                    uint32_t off = kvb + (uint32_t)((nt * 16 + (lane & 15)) * LDQ) * 2 + colb;
                    uint32_t r4[4];
                    uint32_t kh0[2], kh1[2], kl0[2], kl1[2];
                    ldsm4(r4, off);                              // Kh
                    kh0[0] = r4[0]; kh0[1] = r4[2];
                    kh1[0] = r4[1]; kh1[1] = r4[3];
                    ldsm4(r4, off + (uint32_t)KVARR * 2);        // Kl
                    kl0[0] = r4[0]; kl0[1] = r4[2];
                    kl1[0] = r4[1]; kl1[1] = r4[3];
                    mma16816(sf[nt * 2],     qfh[t], kh0);
                    mma16816(sf[nt * 2],     qfh[t], kl0);
                    mma16816(sf[nt * 2],     qfl[t], kh0);
                    mma16816(sf[nt * 2 + 1], qfh[t], kh1);
                    mma16816(sf[nt * 2 + 1], qfh[t], kl1);
                    mma16816(sf[nt * 2 + 1], qfl[t], kh1);
                }
            }

            // ---- scale + causal mask ----
#pragma unroll
            for (int j = 0; j < 8; j++)
#pragma unroll
                for (int q = 0; q < 4; q++)
                    sf[j][q] *= 0.125f;

            const int r0g = q0 + wrow + (lane >> 2);
            const int r1g = r0g + 8;
            if (kt * 64 + 63 > q0 + wrow) {
                const int cbase = kt * 64 + 2 * (lane & 3);
#pragma unroll
                for (int j = 0; j < 8; j++) {
                    int c = cbase + 8 * j;
                    if (c     > r0g) sf[j][0] = -INFINITY;
                    if (c + 1 > r0g) sf[j][1] = -INFINITY;
                    if (c     > r1g) sf[j][2] = -INFINITY;
                    if (c + 1 > r1g) sf[j][3] = -INFINITY;
                }
            }

            // ---- online softmax (rows r0g, r1g) ----
            float rm0 = -INFINITY, rm1 = -INFINITY;
#pragma unroll
            for (int j = 0; j < 8; j++) {
                rm0 = fmaxf(rm0, fmaxf(sf[j][0], sf[j][1]));
                rm1 = fmaxf(rm1, fmaxf(sf[j][2], sf[j][3]));
            }
            rm0 = fmaxf(rm0, __shfl_xor_sync(0xffffffffu, rm0, 1));
            rm0 = fmaxf(rm0, __shfl_xor_sync(0xffffffffu, rm0, 2));
            rm1 = fmaxf(rm1, __shfl_xor_sync(0xffffffffu, rm1, 1));
            rm1 = fmaxf(rm1, __shfl_xor_sync(0xffffffffu, rm1, 2));

            float mn0 = fmaxf(m0, rm0);
            float mn1 = fmaxf(m1, rm1);
            float rs0 = 0.0f, rs1 = 0.0f;
#pragma unroll
            for (int j = 0; j < 8; j++) {
                sf[j][0] = __expf(sf[j][0] - mn0);
                sf[j][1] = __expf(sf[j][1] - mn0);
                sf[j][2] = __expf(sf[j][2] - mn1);
                sf[j][3] = __expf(sf[j][3] - mn1);
                rs0 += sf[j][0] + sf[j][1];
                rs1 += sf[j][2] + sf[j][3];
            }
            rs0 += __shfl_xor_sync(0xffffffffu, rs0, 1);
            rs0 += __shfl_xor_sync(0xffffffffu, rs0, 2);
            rs1 += __shfl_xor_sync(0xffffffffu, rs1, 1);
            rs1 += __shfl_xor_sync(0xffffffffu, rs1, 2);

            float a0 = __expf(m0 - mn0);
            float a1 = __expf(m1 - mn1);
            l0 = l0 * a0 + rs0;
            l1 = l1 * a1 + rs1;
            m0 = mn0;
            m1 = mn1;
#pragma unroll
            for (int j = 0; j < 8; j++) {
                o[j][0] *= a0;
                o[j][1] *= a0;
                o[j][2] *= a1;
                o[j][3] *= a1;
            }

            // ---- pack P (hi/lo) as A-operand fragments, in registers ----
            uint32_t pah[4][4];
            uint32_t pal[4][4];
#pragma unroll
            for (int t = 0; t < 4; t++) {
                split_pack(sf[2*t][0],   sf[2*t][1],   pah[t][0], pal[t][0]);
                split_pack(sf[2*t][2],   sf[2*t][3],   pah[t][1], pal[t][1]);
                split_pack(sf[2*t+1][0], sf[2*t+1][1], pah[t][2], pal[t][2]);
                split_pack(sf[2*t+1][2], sf[2*t+1][3], pah[t][3], pal[t][3]);
            }

            // ---- O += P V  (V via ldmatrix.trans) ----
#pragma unroll
            for (int t = 0; t < 4; t++) {
#pragma unroll
                for (int dt = 0; dt < 4; dt++) {
                    uint32_t off = kvb
                        + (uint32_t)((t * 16 + ((lane & 16) >> 1) + (lane & 7)) * LDQ
                                     + dt * 16 + (lane & 8)) * 2;
                    uint32_t r4[4];
                    uint32_t vh0[2], vh1[2], vl0[2], vl1[2];
                    ldsm4t(r4, off + (uint32_t)(2 * KVARR) * 2);   // Vh
                    vh0[0] = r4[0]; vh0[1] = r4[2];
                    vh1[0] = r4[1]; vh1[1] = r4[3];
                    ldsm4t(r4, off + (uint32_t)(3 * KVARR) * 2);   // Vl
                    vl0[0] = r4[0]; vl0[1] = r4[2];
                    vl1[0] = r4[1]; vl1[1] = r4[3];
                    mma16816(o[dt * 2],     pah[t], vh0);
                    mma16816(o[dt * 2],     pah[t], vl0);
                    mma16816(o[dt * 2],     pal[t], vh0);
                    mma16816(o[dt * 2 + 1], pah[t], vh1);
                    mma16816(o[dt * 2 + 1], pah[t], vl1);
                    mma16816(o[dt * 2 + 1], pal[t], vh1);
                }
            }
        }
    }
#undef ISSUE_KV

    // ---- epilogue: normalize, write bf16 hi/lo [b, s, h*64+d] ----
    const float in0 = 1.0f / l0;
    const float in1 = 1.0f / l1;
    const int r0 = q0 + wrow + (lane >> 2);
    const int bb = bh >> 4;
    const int hh = bh & 15;
#pragma unroll
    for (int j = 0; j < 8; j++) {
        int d = hh * 64 + j * 8 + 2 * (lane & 3);
        size_t i0 = ((size_t)bb * S_ + r0) * D_ + d;
        size_t i1 = i0 + (size_t)8 * D_;
        __nv_bfloat162 h2, l2;
        split2(o[j][0] * in0, o[j][1] * in0, h2, l2);
        *(__nv_bfloat162*)(g_oh + i0) = h2;
        *(__nv_bfloat162*)(g_ol + i0) = l2;
        split2(o[j][2] * in1, o[j][3] * in1, h2, l2);
        *(__nv_bfloat162*)(g_oh + i1) = h2;
        *(__nv_bfloat162*)(g_ol + i1) = l2;
    }
}

// ---------------------------------------------------------------------------
extern "C" void kernel_launch(void* const* d_in, const int* in_sizes, int n_in,
                              void* d_out, int out_size)
{
    const float* x  = (const float*)d_in[0];
    const float* Wq = (const float*)d_in[1];
    const float* bq = (const float*)d_in[2];
    const float* Wk = (const float*)d_in[3];
    const float* bk = (const float*)d_in[4];
    const float* Wv = (const float*)d_in[5];
    const float* bv = (const float*)d_in[6];
    const float* Wo = (const float*)d_in[7];
    const float* bo = (const float*)d_in[8];
    float* out = (float*)d_out;

    static int attr_set = 0;
    if (!attr_set) {
        cudaFuncSetAttribute(gemm_q_kernel, cudaFuncAttributeMaxDynamicSharedMemorySize, GSM);
        cudaFuncSetAttribute(gemm_k_kernel, cudaFuncAttributeMaxDynamicSharedMemorySize, GSM);
        cudaFuncSetAttribute(gemm_v_kernel, cudaFuncAttributeMaxDynamicSharedMemorySize, GSM);
        cudaFuncSetAttribute(gemm_o_kernel, cudaFuncAttributeMaxDynamicSharedMemorySize, GSM);
        cudaFuncSetAttribute(attn_kernel,   cudaFuncAttributeMaxDynamicSharedMemorySize, ASM_BYTES);
        attr_set = 1;
    }

    pack_x_kernel <<<(M_ * D_) / 1024, 256>>>(x);
    pack_wq_kernel<<<(D_ * D_) / 1024, 256>>>(Wq);
    pack_wk_kernel<<<(D_ * D_) / 1024, 256>>>(Wk);
    pack_wv_kernel<<<(D_ * D_) / 1024, 256>>>(Wv);
    pack_wo_kernel<<<(D_ * D_) / 1024, 256>>>(Wo);

    dim3 gg(D_ / 128, M_ / 128);   // (8, 64)
    gemm_q_kernel<<<gg, 256, GSM>>>(bq);
    gemm_k_kernel<<<gg, 256, GSM>>>(bk);
    gemm_v_kernel<<<gg, 256, GSM>>>(bv);

    attn_kernel<<<dim3(S_ / 128, B_ * H_), 256, ASM_BYTES>>>();

    gemm_o_kernel<<<gg, 256, GSM>>>(bo, out);
}

// round 6
// speedup vs baseline: 2.6832x; 1.0201x over previous
#include <cuda_runtime.h>
#include <cuda_bf16.h>
#include <cstdint>
#include <math.h>

#define B_  4
#define S_  2048
#define D_  1024
#define H_  16
#define DK_ 64
#define M_  (B_*S_)

// ---------------------------------------------------------------------------
// Scratch (__device__ globals). All tensors split bf16 hi + lo residual.
// ---------------------------------------------------------------------------
__device__ __nv_bfloat16 g_xh[(size_t)M_*D_];
__device__ __nv_bfloat16 g_xl[(size_t)M_*D_];
__device__ __nv_bfloat16 g_qh[(size_t)M_*D_];
__device__ __nv_bfloat16 g_ql[(size_t)M_*D_];
__device__ __nv_bfloat16 g_kh[(size_t)M_*D_];
__device__ __nv_bfloat16 g_kl[(size_t)M_*D_];
__device__ __nv_bfloat16 g_vh[(size_t)M_*D_];
__device__ __nv_bfloat16 g_vl[(size_t)M_*D_];
__device__ __nv_bfloat16 g_oh[(size_t)M_*D_];
__device__ __nv_bfloat16 g_ol[(size_t)M_*D_];

__device__ __nv_bfloat16 g_wqh[(size_t)D_*D_], g_wql[(size_t)D_*D_];
__device__ __nv_bfloat16 g_wkh[(size_t)D_*D_], g_wkl[(size_t)D_*D_];
__device__ __nv_bfloat16 g_wvh[(size_t)D_*D_], g_wvl[(size_t)D_*D_];
__device__ __nv_bfloat16 g_woh[(size_t)D_*D_], g_wol[(size_t)D_*D_];

// ---------------------------------------------------------------------------
// helpers
// ---------------------------------------------------------------------------
__device__ __forceinline__ void split2(float a, float b,
                                       __nv_bfloat162& h2, __nv_bfloat162& l2)
{
    h2.x = __float2bfloat16(a);
    h2.y = __float2bfloat16(b);
    l2.x = __float2bfloat16(a - __bfloat162float(h2.x));
    l2.y = __float2bfloat16(b - __bfloat162float(h2.y));
}

__device__ __forceinline__ void split_pack(float a, float b, uint32_t& hi, uint32_t& lo)
{
    __nv_bfloat162 h2, l2;
    split2(a, b, h2, l2);
    hi = *(uint32_t*)&h2;
    lo = *(uint32_t*)&l2;
}

__device__ __forceinline__ void ldsm4(uint32_t* r, uint32_t addr)
{
    asm volatile("ldmatrix.sync.aligned.m8n8.x4.shared.b16 {%0,%1,%2,%3}, [%4];"
        : "=r"(r[0]), "=r"(r[1]), "=r"(r[2]), "=r"(r[3]) : "r"(addr));
}

__device__ __forceinline__ void ldsm4t(uint32_t* r, uint32_t addr)
{
    asm volatile("ldmatrix.sync.aligned.m8n8.x4.trans.shared.b16 {%0,%1,%2,%3}, [%4];"
        : "=r"(r[0]), "=r"(r[1]), "=r"(r[2]), "=r"(r[3]) : "r"(addr));
}

__device__ __forceinline__ void mma16816(float* c, const uint32_t* a, const uint32_t* b)
{
    asm volatile("mma.sync.aligned.m16n8k16.row.col.f32.bf16.bf16.f32 "
        "{%0,%1,%2,%3}, {%4,%5,%6,%7}, {%8,%9}, {%0,%1,%2,%3};"
        : "+f"(c[0]), "+f"(c[1]), "+f"(c[2]), "+f"(c[3])
        : "r"(a[0]), "r"(a[1]), "r"(a[2]), "r"(a[3]), "r"(b[0]), "r"(b[1]));
}

__device__ __forceinline__ void cpasync16(uint32_t dst, const void* src)
{
    asm volatile("cp.async.cg.shared.global [%0], [%1], 16;" :: "r"(dst), "l"(src));
}

// ---------------------------------------------------------------------------
// Pack: fp32 -> bf16 hi + lo
// ---------------------------------------------------------------------------
__device__ __forceinline__ void pack_body(const float* __restrict__ src,
                                          __nv_bfloat16* __restrict__ hi,
                                          __nv_bfloat16* __restrict__ lo)
{
    int i = (blockIdx.x * 256 + threadIdx.x) * 4;
    float4 v = *(const float4*)(src + i);
    __nv_bfloat162 h0, l0, h1, l1;
    split2(v.x, v.y, h0, l0);
    split2(v.z, v.w, h1, l1);
    *(__nv_bfloat162*)(hi + i)     = h0;
    *(__nv_bfloat162*)(hi + i + 2) = h1;
    *(__nv_bfloat162*)(lo + i)     = l0;
    *(__nv_bfloat162*)(lo + i + 2) = l1;
}

__global__ __launch_bounds__(256) void pack_x_kernel (const float* __restrict__ s) { pack_body(s, g_xh, g_xl); }
__global__ __launch_bounds__(256) void pack_wq_kernel(const float* __restrict__ s) { pack_body(s, g_wqh, g_wql); }
__global__ __launch_bounds__(256) void pack_wk_kernel(const float* __restrict__ s) { pack_body(s, g_wkh, g_wkl); }
__global__ __launch_bounds__(256) void pack_wv_kernel(const float* __restrict__ s) { pack_body(s, g_wvh, g_wvl); }
__global__ __launch_bounds__(256) void pack_wo_kernel(const float* __restrict__ s) { pack_body(s, g_woh, g_wol); }

// ---------------------------------------------------------------------------
// Tensor-core GEMM (split bf16, 3-pass), cp.async double-buffered.
// __launch_bounds__(256,2): force 2 blocks/SM (reg cap 128). Inner loop keeps
// only one im's A-fragments live to fit the cap without spills.
// ---------------------------------------------------------------------------
#define GLDA 40
#define GT   (128 * GLDA)
#define GSM  (2 * 4 * GT * 2)

template<int MODE>
__device__ __forceinline__ void gemm_tc(const __nv_bfloat16* __restrict__ Xh,
                                        const __nv_bfloat16* __restrict__ Xl,
                                        const __nv_bfloat16* __restrict__ Wh,
                                        const __nv_bfloat16* __restrict__ Wl,
                                        const float* __restrict__ bias,
                                        float* __restrict__ Yf,
                                        __nv_bfloat16* __restrict__ Yh,
                                        __nv_bfloat16* __restrict__ Yl)
{
    extern __shared__ __nv_bfloat16 smem[];

    const int tid  = threadIdx.x;
    const int lane = tid & 31;
    const int w    = tid >> 5;
    const int wm   = (w >> 2) * 64;
    const int wn   = (w & 3) * 32;
    const int row0 = blockIdx.y * 128;
    const int col0 = blockIdx.x * 128;

    float acc[4][4][4];
#pragma unroll
    for (int im = 0; im < 4; im++)
#pragma unroll
        for (int in = 0; in < 4; in++)
#pragma unroll
            for (int q = 0; q < 4; q++)
                acc[im][in][q] = 0.0f;

    const uint32_t aS = (uint32_t)__cvta_generic_to_shared(smem);
    const int cr  = tid >> 2;
    const int cc8 = (tid & 3) * 8;

    const __nv_bfloat16* srcA_h = Xh + (size_t)(row0 + cr) * D_ + cc8;
    const __nv_bfloat16* srcA_l = Xl + (size_t)(row0 + cr) * D_ + cc8;
    const __nv_bfloat16* srcB_h = Wh + (size_t)(col0 + cr) * D_ + cc8;
    const __nv_bfloat16* srcB_l = Wl + (size_t)(col0 + cr) * D_ + cc8;
    const uint32_t dOff   = (uint32_t)(cr * GLDA + cc8) * 2;
    const uint32_t dRow64 = (uint32_t)(64 * GLDA) * 2;

#define ISSUE_COPY(sstage, k0v)                                                   \
    do {                                                                          \
        uint32_t db = aS + (uint32_t)((sstage) * 4 * GT) * 2 + dOff;              \
        cpasync16(db,                           srcA_h + (k0v));                  \
        cpasync16(db + dRow64,                  srcA_h + (k0v) + 64 * D_);        \
        cpasync16(db + (uint32_t)GT*2,          srcA_l + (k0v));                  \
        cpasync16(db + (uint32_t)GT*2 + dRow64, srcA_l + (k0v) + 64 * D_);        \
        cpasync16(db + (uint32_t)GT*4,          srcB_h + (k0v));                  \
        cpasync16(db + (uint32_t)GT*4 + dRow64, srcB_h + (k0v) + 64 * D_);        \
        cpasync16(db + (uint32_t)GT*6,          srcB_l + (k0v));                  \
        cpasync16(db + (uint32_t)GT*6 + dRow64, srcB_l + (k0v) + 64 * D_);        \
        asm volatile("cp.async.commit_group;");                                   \
    } while (0)

    ISSUE_COPY(0, 0);

    for (int kt = 0; kt < D_ / 32; kt++) {
        const int s = kt & 1;
        asm volatile("cp.async.wait_group 0;");
        __syncthreads();
        if (kt + 1 < D_ / 32)
            ISSUE_COPY(s ^ 1, (kt + 1) * 32);

        const uint32_t bAh = aS + (uint32_t)((s * 4 + 0) * GT) * 2;
        const uint32_t bAl = aS + (uint32_t)((s * 4 + 1) * GT) * 2;
        const uint32_t bBh = aS + (uint32_t)((s * 4 + 2) * GT) * 2;
        const uint32_t bBl = aS + (uint32_t)((s * 4 + 3) * GT) * 2;

#pragma unroll
        for (int kc = 0; kc < 2; kc++) {
            const uint32_t colb = (uint32_t)(kc * 16 + ((lane >> 4) << 3)) * 2;

            // B fragments for this kc (16 regs live)
            uint32_t bfh[4][2];
            uint32_t bfl[4][2];
#pragma unroll
            for (int np = 0; np < 2; np++) {
                uint32_t off = (uint32_t)((wn + np * 16 + (lane & 15)) * GLDA) * 2 + colb;
                uint32_t r4[4];
                ldsm4(r4, bBh + off);
                bfh[np * 2 + 0][0] = r4[0];
                bfh[np * 2 + 0][1] = r4[2];
                bfh[np * 2 + 1][0] = r4[1];
                bfh[np * 2 + 1][1] = r4[3];
                ldsm4(r4, bBl + off);
                bfl[np * 2 + 0][0] = r4[0];
                bfl[np * 2 + 0][1] = r4[2];
                bfl[np * 2 + 1][0] = r4[1];
                bfl[np * 2 + 1][1] = r4[3];
            }

            // A fragments one im at a time (8 regs live)
#pragma unroll
            for (int im = 0; im < 4; im++) {
                uint32_t afh[4];
                uint32_t afl[4];
                uint32_t off = (uint32_t)((wm + im * 16 + (lane & 15)) * GLDA) * 2 + colb;
                ldsm4(afh, bAh + off);
                ldsm4(afl, bAl + off);
#pragma unroll
                for (int in = 0; in < 4; in++) {
                    mma16816(acc[im][in], afh, bfh[in]);
                    mma16816(acc[im][in], afh, bfl[in]);
                    mma16816(acc[im][in], afl, bfh[in]);
                }
            }
        }
        __syncthreads();
    }
#undef ISSUE_COPY

    const int r_in = lane >> 2;
    const int c_in = (lane & 3) * 2;
#pragma unroll
    for (int im = 0; im < 4; im++) {
#pragma unroll
        for (int in = 0; in < 4; in++) {
            int rg = row0 + wm + im * 16 + r_in;
            int cg = col0 + wn + in * 8 + c_in;
            float b0 = bias[cg];
            float b1 = bias[cg + 1];
            float2 v0;
            float2 v1;
            v0.x = acc[im][in][0] + b0;
            v0.y = acc[im][in][1] + b1;
            v1.x = acc[im][in][2] + b0;
            v1.y = acc[im][in][3] + b1;
            if (MODE == 0) {
                *(float2*)(Yf + (size_t)rg * D_ + cg)       = v0;
                *(float2*)(Yf + (size_t)(rg + 8) * D_ + cg) = v1;
            } else {
                int hh = cg >> 6;
                int dd = cg & 63;
                int bb = rg >> 11;
                int ss = rg & (S_ - 1);
                size_t base = (((size_t)bb * H_ + hh) * S_ + ss) * DK_ + dd;
                __nv_bfloat162 h2, l2;
                split2(v0.x, v0.y, h2, l2);
                *(__nv_bfloat162*)(Yh + base) = h2;
                *(__nv_bfloat162*)(Yl + base) = l2;
                split2(v1.x, v1.y, h2, l2);
                *(__nv_bfloat162*)(Yh + base + 8 * DK_) = h2;
                *(__nv_bfloat162*)(Yl + base + 8 * DK_) = l2;
            }
        }
    }
}

__global__ __launch_bounds__(256, 2) void gemm_q_kernel(const float* __restrict__ b)
{ gemm_tc<1>(g_xh, g_xl, g_wqh, g_wql, b, nullptr, g_qh, g_ql); }
__global__ __launch_bounds__(256, 2) void gemm_k_kernel(const float* __restrict__ b)
{ gemm_tc<1>(g_xh, g_xl, g_wkh, g_wkl, b, nullptr, g_kh, g_kl); }
__global__ __launch_bounds__(256, 2) void gemm_v_kernel(const float* __restrict__ b)
{ gemm_tc<1>(g_xh, g_xl, g_wvh, g_wvl, b, nullptr, g_vh, g_vl); }
__global__ __launch_bounds__(256, 2) void gemm_o_kernel(const float* __restrict__ b,
                                                        float* __restrict__ out)
{ gemm_tc<0>(g_oh, g_ol, g_woh, g_wol, b, out, nullptr, nullptr); }

// ---------------------------------------------------------------------------
// Tensor-core flash attention (unchanged from round 5).
// ---------------------------------------------------------------------------
#define LDQ   72
#define AQH   0
#define AQL   (128*LDQ)
#define AKV0  (2*128*LDQ)
#define KVARR (64*LDQ)
#define KVST  (4*KVARR)
#define ASM_BYTES ((AKV0 + 2*KVST) * 2)

__global__ __launch_bounds__(256) void attn_kernel()
{
    extern __shared__ __nv_bfloat16 sm[];
    const int tid  = threadIdx.x;
    const int lane = tid & 31;
    const int w    = tid >> 5;
    const int bh   = blockIdx.y;
    const int qt   = blockIdx.x;
    const int q0   = qt * 128;
    const int wrow = w * 16;

    const size_t hb = (size_t)bh * S_ * DK_;
    const uint32_t aS = (uint32_t)__cvta_generic_to_shared(sm);

    {
        int a = tid >> 7;
        int r = tid & 127;
        const __nv_bfloat16* src = (a ? g_ql : g_qh) + hb + (size_t)(q0 + r) * DK_;
        uint32_t dst = aS + (uint32_t)((a ? AQL : AQH) + r * LDQ) * 2;
#pragma unroll
        for (int c = 0; c < 8; c++)
            cpasync16(dst + c * 16, src + c * 8);
    }

    const int kv_a = tid >> 6;
    const int kv_r = tid & 63;
    const __nv_bfloat16* kv_src =
        ((kv_a == 0) ? g_kh : (kv_a == 1) ? g_kl : (kv_a == 2) ? g_vh : g_vl)
        + hb + (size_t)kv_r * DK_;
    const uint32_t kv_doff = (uint32_t)(AKV0 + kv_a * KVARR + kv_r * LDQ) * 2;

#define ISSUE_KV(kt_, st_)                                                        \
    do {                                                                          \
        const __nv_bfloat16* sp = kv_src + (size_t)(kt_) * 64 * DK_;              \
        uint32_t dst = aS + kv_doff + (uint32_t)((st_) * KVST) * 2;               \
        _Pragma("unroll")                                                         \
        for (int c = 0; c < 8; c++)                                               \
            cpasync16(dst + c * 16, sp + c * 8);                                  \
        asm volatile("cp.async.commit_group;");                                   \
    } while (0)

    ISSUE_KV(0, 0);

    const int ktmax = 2 * qt + 1;

    float o[8][4];
#pragma unroll
    for (int j = 0; j < 8; j++)
#pragma unroll
        for (int q = 0; q < 4; q++)
            o[j][q] = 0.0f;
    float m0 = -INFINITY, m1 = -INFINITY, l0 = 0.0f, l1 = 0.0f;

    uint32_t qfh[4][4];
    uint32_t qfl[4][4];

    for (int kt = 0; kt <= ktmax; kt++) {
        const int st = kt & 1;
        asm volatile("cp.async.wait_group 0;");
        __syncthreads();
        if (kt < ktmax)
            ISSUE_KV(kt + 1, st ^ 1);

        if (kt == 0) {
#pragma unroll
            for (int t = 0; t < 4; t++) {
                uint32_t off = (uint32_t)((wrow + (lane & 15)) * LDQ
                                          + t * 16 + ((lane >> 4) << 3)) * 2;
                ldsm4(qfh[t], aS + (uint32_t)AQH * 2 + off);
                ldsm4(qfl[t], aS + (uint32_t)AQL * 2 + off);
            }
        }

        if (kt * 64 <= q0 + wrow + 15) {
            const uint32_t kvb = aS + (uint32_t)(AKV0 + st * KVST) * 2;

            float sf[8][4];
#pragma unroll
            for (int j = 0; j < 8; j++)
#pragma unroll
                for (int q = 0; q < 4; q++)
                    sf[j][q] = 0.0f;

#pragma unroll
            for (int t = 0; t < 4; t++) {
                const uint32_t colb = (uint32_t)(t * 16 + ((lane >> 4) << 3)) * 2;
#pragma unroll
                for (int nt = 0; nt < 4; nt++) {
                    uint32_t off = kvb + (uint32_t)((nt * 16 + (lane & 15)) * LDQ) * 2 + colb;
                    uint32_t r4[4];
                    uint32_t kh0[2], kh1[2], kl0[2], kl1[2];
                    ldsm4(r4, off);
                    kh0[0] = r4[0]; kh0[1] = r4[2];
                    kh1[0] = r4[1]; kh1[1] = r4[3];
                    ldsm4(r4, off + (uint32_t)KVARR * 2);
                    kl0[0] = r4[0]; kl0[1] = r4[2];
                    kl1[0] = r4[1]; kl1[1] = r4[3];
                    mma16816(sf[nt * 2],     qfh[t], kh0);
                    mma16816(sf[nt * 2],     qfh[t], kl0);
                    mma16816(sf[nt * 2],     qfl[t], kh0);
                    mma16816(sf[nt * 2 + 1], qfh[t], kh1);
                    mma16816(sf[nt * 2 + 1], qfh[t], kl1);
                    mma16816(sf[nt * 2 + 1], qfl[t], kh1);
                }
            }

#pragma unroll
            for (int j = 0; j < 8; j++)
#pragma unroll
                for (int q = 0; q < 4; q++)
                    sf[j][q] *= 0.125f;

            const int r0g = q0 + wrow + (lane >> 2);
            const int r1g = r0g + 8;
            if (kt * 64 + 63 > q0 + wrow) {
                const int cbase = kt * 64 + 2 * (lane & 3);
#pragma unroll
                for (int j = 0; j < 8; j++) {
                    int c = cbase + 8 * j;
                    if (c     > r0g) sf[j][0] = -INFINITY;
                    if (c + 1 > r0g) sf[j][1] = -INFINITY;
                    if (c     > r1g) sf[j][2] = -INFINITY;
                    if (c + 1 > r1g) sf[j][3] = -INFINITY;
                }
            }

            float rm0 = -INFINITY, rm1 = -INFINITY;
#pragma unroll
            for (int j = 0; j < 8; j++) {
                rm0 = fmaxf(rm0, fmaxf(sf[j][0], sf[j][1]));
                rm1 = fmaxf(rm1, fmaxf(sf[j][2], sf[j][3]));
            }
            rm0 = fmaxf(rm0, __shfl_xor_sync(0xffffffffu, rm0, 1));
            rm0 = fmaxf(rm0, __shfl_xor_sync(0xffffffffu, rm0, 2));
            rm1 = fmaxf(rm1, __shfl_xor_sync(0xffffffffu, rm1, 1));
            rm1 = fmaxf(rm1, __shfl_xor_sync(0xffffffffu, rm1, 2));

            float mn0 = fmaxf(m0, rm0);
            float mn1 = fmaxf(m1, rm1);
            float rs0 = 0.0f, rs1 = 0.0f;
#pragma unroll
            for (int j = 0; j < 8; j++) {
                sf[j][0] = __expf(sf[j][0] - mn0);
                sf[j][1] = __expf(sf[j][1] - mn0);
                sf[j][2] = __expf(sf[j][2] - mn1);
                sf[j][3] = __expf(sf[j][3] - mn1);
                rs0 += sf[j][0] + sf[j][1];
                rs1 += sf[j][2] + sf[j][3];
            }
            rs0 += __shfl_xor_sync(0xffffffffu, rs0, 1);
            rs0 += __shfl_xor_sync(0xffffffffu, rs0, 2);
            rs1 += __shfl_xor_sync(0xffffffffu, rs1, 1);
            rs1 += __shfl_xor_sync(0xffffffffu, rs1, 2);

            float a0 = __expf(m0 - mn0);
            float a1 = __expf(m1 - mn1);
            l0 = l0 * a0 + rs0;
            l1 = l1 * a1 + rs1;
            m0 = mn0;
            m1 = mn1;
#pragma unroll
            for (int j = 0; j < 8; j++) {
                o[j][0] *= a0;
                o[j][1] *= a0;
                o[j][2] *= a1;
                o[j][3] *= a1;
            }

            uint32_t pah[4][4];
            uint32_t pal[4][4];
#pragma unroll
            for (int t = 0; t < 4; t++) {
                split_pack(sf[2*t][0],   sf[2*t][1],   pah[t][0], pal[t][0]);
                split_pack(sf[2*t][2],   sf[2*t][3],   pah[t][1], pal[t][1]);
                split_pack(sf[2*t+1][0], sf[2*t+1][1], pah[t][2], pal[t][2]);
                split_pack(sf[2*t+1][2], sf[2*t+1][3], pah[t][3], pal[t][3]);
            }

#pragma unroll
            for (int t = 0; t < 4; t++) {
#pragma unroll
                for (int dt = 0; dt < 4; dt++) {
                    uint32_t off = kvb
                        + (uint32_t)((t * 16 + ((lane & 16) >> 1) + (lane & 7)) * LDQ
                                     + dt * 16 + (lane & 8)) * 2;
                    uint32_t r4[4];
                    uint32_t vh0[2], vh1[2], vl0[2], vl1[2];
                    ldsm4t(r4, off + (uint32_t)(2 * KVARR) * 2);
                    vh0[0] = r4[0]; vh0[1] = r4[2];
                    vh1[0] = r4[1]; vh1[1] = r4[3];
                    ldsm4t(r4, off + (uint32_t)(3 * KVARR) * 2);
                    vl0[0] = r4[0]; vl0[1] = r4[2];
                    vl1[0] = r4[1]; vl1[1] = r4[3];
                    mma16816(o[dt * 2],     pah[t], vh0);
                    mma16816(o[dt * 2],     pah[t], vl0);
                    mma16816(o[dt * 2],     pal[t], vh0);
                    mma16816(o[dt * 2 + 1], pah[t], vh1);
                    mma16816(o[dt * 2 + 1], pah[t], vl1);
                    mma16816(o[dt * 2 + 1], pal[t], vh1);
                }
            }
        }
    }
#undef ISSUE_KV

    const float in0 = 1.0f / l0;
    const float in1 = 1.0f / l1;
    const int r0 = q0 + wrow + (lane >> 2);
    const int bb = bh >> 4;
    const int hh = bh & 15;
#pragma unroll
    for (int j = 0; j < 8; j++) {
        int d = hh * 64 + j * 8 + 2 * (lane & 3);
        size_t i0 = ((size_t)bb * S_ + r0) * D_ + d;
        size_t i1 = i0 + (size_t)8 * D_;
        __nv_bfloat162 h2, l2;
        split2(o[j][0] * in0, o[j][1] * in0, h2, l2);
        *(__nv_bfloat162*)(g_oh + i0) = h2;
        *(__nv_bfloat162*)(g_ol + i0) = l2;
        split2(o[j][2] * in1, o[j][3] * in1, h2, l2);
        *(__nv_bfloat162*)(g_oh + i1) = h2;
        *(__nv_bfloat162*)(g_ol + i1) = l2;
    }
}

// ---------------------------------------------------------------------------
extern "C" void kernel_launch(void* const* d_in, const int* in_sizes, int n_in,
                              void* d_out, int out_size)
{
    const float* x  = (const float*)d_in[0];
    const float* Wq = (const float*)d_in[1];
    const float* bq = (const float*)d_in[2];
    const float* Wk = (const float*)d_in[3];
    const float* bk = (const float*)d_in[4];
    const float* Wv = (const float*)d_in[5];
    const float* bv = (const float*)d_in[6];
    const float* Wo = (const float*)d_in[7];
    const float* bo = (const float*)d_in[8];
    float* out = (float*)d_out;

    static int attr_set = 0;
    if (!attr_set) {
        cudaFuncSetAttribute(gemm_q_kernel, cudaFuncAttributeMaxDynamicSharedMemorySize, GSM);
        cudaFuncSetAttribute(gemm_k_kernel, cudaFuncAttributeMaxDynamicSharedMemorySize, GSM);
        cudaFuncSetAttribute(gemm_v_kernel, cudaFuncAttributeMaxDynamicSharedMemorySize, GSM);
        cudaFuncSetAttribute(gemm_o_kernel, cudaFuncAttributeMaxDynamicSharedMemorySize, GSM);
        cudaFuncSetAttribute(attn_kernel,   cudaFuncAttributeMaxDynamicSharedMemorySize, ASM_BYTES);
        attr_set = 1;
    }

    dim3 gg(D_ / 128, M_ / 128);   // (8, 64)

    // Launch order arranged so the ncu capture (empirically launch index 3)
    // lands on gemm_q_kernel.
    pack_x_kernel <<<(M_ * D_) / 1024, 256>>>(x);    // 0
    pack_wq_kernel<<<(D_ * D_) / 1024, 256>>>(Wq);   // 1
    pack_wk_kernel<<<(D_ * D_) / 1024, 256>>>(Wk);   // 2
    gemm_q_kernel<<<gg, 256, GSM>>>(bq);             // 3  <- ncu target
    pack_wv_kernel<<<(D_ * D_) / 1024, 256>>>(Wv);   // 4
    pack_wo_kernel<<<(D_ * D_) / 1024, 256>>>(Wo);   // 5
    gemm_k_kernel<<<gg, 256, GSM>>>(bk);             // 6
    gemm_v_kernel<<<gg, 256, GSM>>>(bv);             // 7

    attn_kernel<<<dim3(S_ / 128, B_ * H_), 256, ASM_BYTES>>>();   // 8

    gemm_o_kernel<<<gg, 256, GSM>>>(bo, out);        // 9
}

// round 8
// speedup vs baseline: 2.8108x; 1.0476x over previous
#include <cuda_runtime.h>
#include <cuda_bf16.h>
#include <cstdint>
#include <math.h>

#define B_  4
#define S_  2048
#define D_  1024
#define H_  16
#define DK_ 64
#define M_  (B_*S_)

// ---------------------------------------------------------------------------
// Scratch (__device__ globals). All tensors split bf16 hi + lo residual.
// ---------------------------------------------------------------------------
__device__ __nv_bfloat16 g_xh[(size_t)M_*D_];
__device__ __nv_bfloat16 g_xl[(size_t)M_*D_];
__device__ __nv_bfloat16 g_qh[(size_t)M_*D_];
__device__ __nv_bfloat16 g_ql[(size_t)M_*D_];
__device__ __nv_bfloat16 g_kh[(size_t)M_*D_];
__device__ __nv_bfloat16 g_kl[(size_t)M_*D_];
__device__ __nv_bfloat16 g_vh[(size_t)M_*D_];
__device__ __nv_bfloat16 g_vl[(size_t)M_*D_];
__device__ __nv_bfloat16 g_oh[(size_t)M_*D_];
__device__ __nv_bfloat16 g_ol[(size_t)M_*D_];

__device__ __nv_bfloat16 g_wqh[(size_t)D_*D_], g_wql[(size_t)D_*D_];
__device__ __nv_bfloat16 g_wkh[(size_t)D_*D_], g_wkl[(size_t)D_*D_];
__device__ __nv_bfloat16 g_wvh[(size_t)D_*D_], g_wvl[(size_t)D_*D_];
__device__ __nv_bfloat16 g_woh[(size_t)D_*D_], g_wol[(size_t)D_*D_];

// ---------------------------------------------------------------------------
// helpers
// ---------------------------------------------------------------------------
__device__ __forceinline__ void split2(float a, float b,
                                       __nv_bfloat162& h2, __nv_bfloat162& l2)
{
    h2.x = __float2bfloat16(a);
    h2.y = __float2bfloat16(b);
    l2.x = __float2bfloat16(a - __bfloat162float(h2.x));
    l2.y = __float2bfloat16(b - __bfloat162float(h2.y));
}

__device__ __forceinline__ void split_pack(float a, float b, uint32_t& hi, uint32_t& lo)
{
    __nv_bfloat162 h2, l2;
    split2(a, b, h2, l2);
    hi = *(uint32_t*)&h2;
    lo = *(uint32_t*)&l2;
}

__device__ __forceinline__ void ldsm4(uint32_t* r, uint32_t addr)
{
    asm volatile("ldmatrix.sync.aligned.m8n8.x4.shared.b16 {%0,%1,%2,%3}, [%4];"
        : "=r"(r[0]), "=r"(r[1]), "=r"(r[2]), "=r"(r[3]) : "r"(addr));
}

__device__ __forceinline__ void ldsm4t(uint32_t* r, uint32_t addr)
{
    asm volatile("ldmatrix.sync.aligned.m8n8.x4.trans.shared.b16 {%0,%1,%2,%3}, [%4];"
        : "=r"(r[0]), "=r"(r[1]), "=r"(r[2]), "=r"(r[3]) : "r"(addr));
}

__device__ __forceinline__ void mma16816(float* c, const uint32_t* a, const uint32_t* b)
{
    asm volatile("mma.sync.aligned.m16n8k16.row.col.f32.bf16.bf16.f32 "
        "{%0,%1,%2,%3}, {%4,%5,%6,%7}, {%8,%9}, {%0,%1,%2,%3};"
        : "+f"(c[0]), "+f"(c[1]), "+f"(c[2]), "+f"(c[3])
        : "r"(a[0]), "r"(a[1]), "r"(a[2]), "r"(a[3]), "r"(b[0]), "r"(b[1]));
}

__device__ __forceinline__ void cpasync16(uint32_t dst, const void* src)
{
    asm volatile("cp.async.cg.shared.global [%0], [%1], 16;" :: "r"(dst), "l"(src));
}

// ---------------------------------------------------------------------------
// Pack kernels: fp32 -> bf16 hi + lo
// ---------------------------------------------------------------------------
__device__ __forceinline__ void pack_body(const float* __restrict__ src,
                                          __nv_bfloat16* __restrict__ hi,
                                          __nv_bfloat16* __restrict__ lo,
                                          int blk)
{
    int i = (blk * 256 + threadIdx.x) * 4;
    float4 v = *(const float4*)(src + i);
    __nv_bfloat162 h0, l0, h1, l1;
    split2(v.x, v.y, h0, l0);
    split2(v.z, v.w, h1, l1);
    *(__nv_bfloat162*)(hi + i)     = h0;
    *(__nv_bfloat162*)(hi + i + 2) = h1;
    *(__nv_bfloat162*)(lo + i)     = l0;
    *(__nv_bfloat162*)(lo + i + 2) = l1;
}

__global__ __launch_bounds__(256) void pack_x_kernel(const float* __restrict__ s)
{ pack_body(s, g_xh, g_xl, blockIdx.x); }

__global__ __launch_bounds__(256) void pack_wo_kernel(const float* __restrict__ s)
{ pack_body(s, g_woh, g_wol, blockIdx.x); }

// packs Wq, Wk, Wv in one launch: 1024 blocks each
__global__ __launch_bounds__(256) void pack_wqkv_kernel(const float* __restrict__ wq,
                                                        const float* __restrict__ wk,
                                                        const float* __restrict__ wv)
{
    int which = blockIdx.x >> 10;
    int blk   = blockIdx.x & 1023;
    const float* src = (which == 0) ? wq : (which == 1) ? wk : wv;
    __nv_bfloat16* hi = (which == 0) ? g_wqh : (which == 1) ? g_wkh : g_wvh;
    __nv_bfloat16* lo = (which == 0) ? g_wql : (which == 1) ? g_wkl : g_wvl;
    pack_body(src, hi, lo, blk);
}

// ---------------------------------------------------------------------------
// Tensor-core GEMM body (split bf16, 3-pass), cp.async double-buffered.
// Pass-major inner ordering: consecutive HMMA hit different accumulators.
// ---------------------------------------------------------------------------
#define GLDA 40
#define GT   (128 * GLDA)
#define GSM  (2 * 4 * GT * 2)

template<int MODE>
__device__ __forceinline__ void gemm_tc(const __nv_bfloat16* __restrict__ Xh,
                                        const __nv_bfloat16* __restrict__ Xl,
                                        const __nv_bfloat16* __restrict__ Wh,
                                        const __nv_bfloat16* __restrict__ Wl,
                                        const float* __restrict__ bias,
                                        float* __restrict__ Yf,
                                        __nv_bfloat16* __restrict__ Yh,
                                        __nv_bfloat16* __restrict__ Yl,
                                        int row0, int col0)
{
    extern __shared__ __nv_bfloat16 smem[];

    const int tid  = threadIdx.x;
    const int lane = tid & 31;
    const int w    = tid >> 5;
    const int wm   = (w >> 2) * 64;
    const int wn   = (w & 3) * 32;

    float acc[4][4][4];
#pragma unroll
    for (int im = 0; im < 4; im++)
#pragma unroll
        for (int in = 0; in < 4; in++)
#pragma unroll
            for (int q = 0; q < 4; q++)
                acc[im][in][q] = 0.0f;

    const uint32_t aS = (uint32_t)__cvta_generic_to_shared(smem);
    const int cr  = tid >> 2;
    const int cc8 = (tid & 3) * 8;

    const __nv_bfloat16* srcA_h = Xh + (size_t)(row0 + cr) * D_ + cc8;
    const __nv_bfloat16* srcA_l = Xl + (size_t)(row0 + cr) * D_ + cc8;
    const __nv_bfloat16* srcB_h = Wh + (size_t)(col0 + cr) * D_ + cc8;
    const __nv_bfloat16* srcB_l = Wl + (size_t)(col0 + cr) * D_ + cc8;
    const uint32_t dOff   = (uint32_t)(cr * GLDA + cc8) * 2;
    const uint32_t dRow64 = (uint32_t)(64 * GLDA) * 2;

#define ISSUE_COPY(sstage, k0v)                                                   \
    do {                                                                          \
        uint32_t db = aS + (uint32_t)((sstage) * 4 * GT) * 2 + dOff;              \
        cpasync16(db,                           srcA_h + (k0v));                  \
        cpasync16(db + dRow64,                  srcA_h + (k0v) + 64 * D_);        \
        cpasync16(db + (uint32_t)GT*2,          srcA_l + (k0v));                  \
        cpasync16(db + (uint32_t)GT*2 + dRow64, srcA_l + (k0v) + 64 * D_);        \
        cpasync16(db + (uint32_t)GT*4,          srcB_h + (k0v));                  \
        cpasync16(db + (uint32_t)GT*4 + dRow64, srcB_h + (k0v) + 64 * D_);        \
        cpasync16(db + (uint32_t)GT*6,          srcB_l + (k0v));                  \
        cpasync16(db + (uint32_t)GT*6 + dRow64, srcB_l + (k0v) + 64 * D_);        \
        asm volatile("cp.async.commit_group;");                                   \
    } while (0)

    ISSUE_COPY(0, 0);

    for (int kt = 0; kt < D_ / 32; kt++) {
        const int s = kt & 1;
        asm volatile("cp.async.wait_group 0;");
        __syncthreads();
        if (kt + 1 < D_ / 32)
            ISSUE_COPY(s ^ 1, (kt + 1) * 32);

        const uint32_t bAh = aS + (uint32_t)((s * 4 + 0) * GT) * 2;
        const uint32_t bAl = aS + (uint32_t)((s * 4 + 1) * GT) * 2;
        const uint32_t bBh = aS + (uint32_t)((s * 4 + 2) * GT) * 2;
        const uint32_t bBl = aS + (uint32_t)((s * 4 + 3) * GT) * 2;

#pragma unroll
        for (int kc = 0; kc < 2; kc++) {
            const uint32_t colb = (uint32_t)(kc * 16 + ((lane >> 4) << 3)) * 2;

            uint32_t bfh[4][2];
            uint32_t bfl[4][2];
#pragma unroll
            for (int np = 0; np < 2; np++) {
                uint32_t off = (uint32_t)((wn + np * 16 + (lane & 15)) * GLDA) * 2 + colb;
                uint32_t r4[4];
                ldsm4(r4, bBh + off);
                bfh[np * 2 + 0][0] = r4[0];
                bfh[np * 2 + 0][1] = r4[2];
                bfh[np * 2 + 1][0] = r4[1];
                bfh[np * 2 + 1][1] = r4[3];
                ldsm4(r4, bBl + off);
                bfl[np * 2 + 0][0] = r4[0];
                bfl[np * 2 + 0][1] = r4[2];
                bfl[np * 2 + 1][0] = r4[1];
                bfl[np * 2 + 1][1] = r4[3];
            }

#pragma unroll
            for (int im = 0; im < 4; im++) {
                uint32_t afh[4];
                uint32_t afl[4];
                uint32_t off = (uint32_t)((wm + im * 16 + (lane & 15)) * GLDA) * 2 + colb;
                ldsm4(afh, bAh + off);
                ldsm4(afl, bAl + off);
                // pass-major: consecutive mma target different accumulators
#pragma unroll
                for (int in = 0; in < 4; in++)
                    mma16816(acc[im][in], afh, bfh[in]);
#pragma unroll
                for (int in = 0; in < 4; in++)
                    mma16816(acc[im][in], afh, bfl[in]);
#pragma unroll
                for (int in = 0; in < 4; in++)
                    mma16816(acc[im][in], afl, bfh[in]);
            }
        }
        __syncthreads();
    }
#undef ISSUE_COPY

    const int r_in = lane >> 2;
    const int c_in = (lane & 3) * 2;
#pragma unroll
    for (int im = 0; im < 4; im++) {
#pragma unroll
        for (int in = 0; in < 4; in++) {
            int rg = row0 + wm + im * 16 + r_in;
            int cg = col0 + wn + in * 8 + c_in;
            float b0 = bias[cg];
            float b1 = bias[cg + 1];
            float2 v0;
            float2 v1;
            v0.x = acc[im][in][0] + b0;
            v0.y = acc[im][in][1] + b1;
            v1.x = acc[im][in][2] + b0;
            v1.y = acc[im][in][3] + b1;
            if (MODE == 0) {
                *(float2*)(Yf + (size_t)rg * D_ + cg)       = v0;
                *(float2*)(Yf + (size_t)(rg + 8) * D_ + cg) = v1;
            } else {
                int hh = cg >> 6;
                int dd = cg & 63;
                int bb = rg >> 11;
                int ss = rg & (S_ - 1);
                size_t base = (((size_t)bb * H_ + hh) * S_ + ss) * DK_ + dd;
                __nv_bfloat162 h2, l2;
                split2(v0.x, v0.y, h2, l2);
                *(__nv_bfloat162*)(Yh + base) = h2;
                *(__nv_bfloat162*)(Yl + base) = l2;
                split2(v1.x, v1.y, h2, l2);
                *(__nv_bfloat162*)(Yh + base + 8 * DK_) = h2;
                *(__nv_bfloat162*)(Yl + base + 8 * DK_) = l2;
            }
        }
    }
}

// Fused Q/K/V projection: grid (24, 64); blockIdx.x>>3 selects the weight.
__global__ __launch_bounds__(256, 2) void gemm_qkv_kernel(const float* __restrict__ bq,
                                                          const float* __restrict__ bk,
                                                          const float* __restrict__ bv)
{
    const int which = blockIdx.x >> 3;
    const int col0  = (blockIdx.x & 7) * 128;
    const int row0  = blockIdx.y * 128;
    const __nv_bfloat16* Wh = (which == 0) ? g_wqh : (which == 1) ? g_wkh : g_wvh;
    const __nv_bfloat16* Wl = (which == 0) ? g_wql : (which == 1) ? g_wkl : g_wvl;
    const float* bias       = (which == 0) ? bq    : (which == 1) ? bk    : bv;
    __nv_bfloat16* Yh       = (which == 0) ? g_qh  : (which == 1) ? g_kh  : g_vh;
    __nv_bfloat16* Yl       = (which == 0) ? g_ql  : (which == 1) ? g_kl  : g_vl;
    gemm_tc<1>(g_xh, g_xl, Wh, Wl, bias, nullptr, Yh, Yl, row0, col0);
}

__global__ __launch_bounds__(256, 2) void gemm_o_kernel(const float* __restrict__ b,
                                                        float* __restrict__ out)
{
    gemm_tc<0>(g_oh, g_ol, g_woh, g_wol, b, out, nullptr, nullptr,
               blockIdx.y * 128, blockIdx.x * 128);
}

// ---------------------------------------------------------------------------
// Tensor-core flash attention (round-5 core, pass-major mma ordering).
// ---------------------------------------------------------------------------
#define LDQ   72
#define AQH   0
#define AQL   (128*LDQ)
#define AKV0  (2*128*LDQ)
#define KVARR (64*LDQ)
#define KVST  (4*KVARR)
#define ASM_BYTES ((AKV0 + 2*KVST) * 2)

__global__ __launch_bounds__(256) void attn_kernel()
{
    extern __shared__ __nv_bfloat16 sm[];
    const int tid  = threadIdx.x;
    const int lane = tid & 31;
    const int w    = tid >> 5;
    const int bh   = blockIdx.y;
    const int qt   = blockIdx.x;
    const int q0   = qt * 128;
    const int wrow = w * 16;

    const size_t hb = (size_t)bh * S_ * DK_;
    const uint32_t aS = (uint32_t)__cvta_generic_to_shared(sm);

    {
        int a = tid >> 7;
        int r = tid & 127;
        const __nv_bfloat16* src = (a ? g_ql : g_qh) + hb + (size_t)(q0 + r) * DK_;
        uint32_t dst = aS + (uint32_t)((a ? AQL : AQH) + r * LDQ) * 2;
#pragma unroll
        for (int c = 0; c < 8; c++)
            cpasync16(dst + c * 16, src + c * 8);
    }

    const int kv_a = tid >> 6;
    const int kv_r = tid & 63;
    const __nv_bfloat16* kv_src =
        ((kv_a == 0) ? g_kh : (kv_a == 1) ? g_kl : (kv_a == 2) ? g_vh : g_vl)
        + hb + (size_t)kv_r * DK_;
    const uint32_t kv_doff = (uint32_t)(AKV0 + kv_a * KVARR + kv_r * LDQ) * 2;

#define ISSUE_KV(kt_, st_)                                                        \
    do {                                                                          \
        const __nv_bfloat16* sp = kv_src + (size_t)(kt_) * 64 * DK_;              \
        uint32_t dst = aS + kv_doff + (uint32_t)((st_) * KVST) * 2;               \
        _Pragma("unroll")                                                         \
        for (int c = 0; c < 8; c++)                                               \
            cpasync16(dst + c * 16, sp + c * 8);                                  \
        asm volatile("cp.async.commit_group;");                                   \
    } while (0)

    ISSUE_KV(0, 0);

    const int ktmax = 2 * qt + 1;

    float o[8][4];
#pragma unroll
    for (int j = 0; j < 8; j++)
#pragma unroll
        for (int q = 0; q < 4; q++)
            o[j][q] = 0.0f;
    float m0 = -INFINITY, m1 = -INFINITY, l0 = 0.0f, l1 = 0.0f;

    uint32_t qfh[4][4];
    uint32_t qfl[4][4];

    for (int kt = 0; kt <= ktmax; kt++) {
        const int st = kt & 1;
        asm volatile("cp.async.wait_group 0;");
        __syncthreads();
        if (kt < ktmax)
            ISSUE_KV(kt + 1, st ^ 1);

        if (kt == 0) {
#pragma unroll
            for (int t = 0; t < 4; t++) {
                uint32_t off = (uint32_t)((wrow + (lane & 15)) * LDQ
                                          + t * 16 + ((lane >> 4) << 3)) * 2;
                ldsm4(qfh[t], aS + (uint32_t)AQH * 2 + off);
                ldsm4(qfl[t], aS + (uint32_t)AQL * 2 + off);
            }
        }

        if (kt * 64 <= q0 + wrow + 15) {
            const uint32_t kvb = aS + (uint32_t)(AKV0 + st * KVST) * 2;

            float sf[8][4];
#pragma unroll
            for (int j = 0; j < 8; j++)
#pragma unroll
                for (int q = 0; q < 4; q++)
                    sf[j][q] = 0.0f;

#pragma unroll
            for (int t = 0; t < 4; t++) {
                const uint32_t colb = (uint32_t)(t * 16 + ((lane >> 4) << 3)) * 2;
#pragma unroll
                for (int nt = 0; nt < 4; nt++) {
                    uint32_t off = kvb + (uint32_t)((nt * 16 + (lane & 15)) * LDQ) * 2 + colb;
                    uint32_t r4[4];
                    uint32_t kh0[2], kh1[2], kl0[2], kl1[2];
                    ldsm4(r4, off);
                    kh0[0] = r4[0]; kh0[1] = r4[2];
                    kh1[0] = r4[1]; kh1[1] = r4[3];
                    ldsm4(r4, off + (uint32_t)KVARR * 2);
                    kl0[0] = r4[0]; kl0[1] = r4[2];
                    kl1[0] = r4[1]; kl1[1] = r4[3];
                    // pass-major (alternate accumulators)
                    mma16816(sf[nt * 2],     qfh[t], kh0);
                    mma16816(sf[nt * 2 + 1], qfh[t], kh1);
                    mma16816(sf[nt * 2],     qfh[t], kl0);
                    mma16816(sf[nt * 2 + 1], qfh[t], kl1);
                    mma16816(sf[nt * 2],     qfl[t], kh0);
                    mma16816(sf[nt * 2 + 1], qfl[t], kh1);
                }
            }

#pragma unroll
            for (int j = 0; j < 8; j++)
#pragma unroll
                for (int q = 0; q < 4; q++)
                    sf[j][q] *= 0.125f;

            const int r0g = q0 + wrow + (lane >> 2);
            const int r1g = r0g + 8;
            if (kt * 64 + 63 > q0 + wrow) {
                const int cbase = kt * 64 + 2 * (lane & 3);
#pragma unroll
                for (int j = 0; j < 8; j++) {
                    int c = cbase + 8 * j;
                    if (c     > r0g) sf[j][0] = -INFINITY;
                    if (c + 1 > r0g) sf[j][1] = -INFINITY;
                    if (c     > r1g) sf[j][2] = -INFINITY;
                    if (c + 1 > r1g) sf[j][3] = -INFINITY;
                }
            }

            float rm0 = -INFINITY, rm1 = -INFINITY;
#pragma unroll
            for (int j = 0; j < 8; j++) {
                rm0 = fmaxf(rm0, fmaxf(sf[j][0], sf[j][1]));
                rm1 = fmaxf(rm1, fmaxf(sf[j][2], sf[j][3]));
            }
            rm0 = fmaxf(rm0, __shfl_xor_sync(0xffffffffu, rm0, 1));
            rm0 = fmaxf(rm0, __shfl_xor_sync(0xffffffffu, rm0, 2));
            rm1 = fmaxf(rm1, __shfl_xor_sync(0xffffffffu, rm1, 1));
            rm1 = fmaxf(rm1, __shfl_xor_sync(0xffffffffu, rm1, 2));

            float mn0 = fmaxf(m0, rm0);
            float mn1 = fmaxf(m1, rm1);
            float rs0 = 0.0f, rs1 = 0.0f;
#pragma unroll
            for (int j = 0; j < 8; j++) {
                sf[j][0] = __expf(sf[j][0] - mn0);
                sf[j][1] = __expf(sf[j][1] - mn0);
                sf[j][2] = __expf(sf[j][2] - mn1);
                sf[j][3] = __expf(sf[j][3] - mn1);
                rs0 += sf[j][0] + sf[j][1];
                rs1 += sf[j][2] + sf[j][3];
            }
            rs0 += __shfl_xor_sync(0xffffffffu, rs0, 1);
            rs0 += __shfl_xor_sync(0xffffffffu, rs0, 2);
            rs1 += __shfl_xor_sync(0xffffffffu, rs1, 1);
            rs1 += __shfl_xor_sync(0xffffffffu, rs1, 2);

            float a0 = __expf(m0 - mn0);
            float a1 = __expf(m1 - mn1);
            l0 = l0 * a0 + rs0;
            l1 = l1 * a1 + rs1;
            m0 = mn0;
            m1 = mn1;
#pragma unroll
            for (int j = 0; j < 8; j++) {
                o[j][0] *= a0;
                o[j][1] *= a0;
                o[j][2] *= a1;
                o[j][3] *= a1;
            }

            uint32_t pah[4][4];
            uint32_t pal[4][4];
#pragma unroll
            for (int t = 0; t < 4; t++) {
                split_pack(sf[2*t][0],   sf[2*t][1],   pah[t][0], pal[t][0]);
                split_pack(sf[2*t][2],   sf[2*t][3],   pah[t][1], pal[t][1]);
                split_pack(sf[2*t+1][0], sf[2*t+1][1], pah[t][2], pal[t][2]);
                split_pack(sf[2*t+1][2], sf[2*t+1][3], pah[t][3], pal[t][3]);
            }

#pragma unroll
            for (int t = 0; t < 4; t++) {
#pragma unroll
                for (int dt = 0; dt < 4; dt++) {
                    uint32_t off = kvb
                        + (uint32_t)((t * 16 + ((lane & 16) >> 1) + (lane & 7)) * LDQ
                                     + dt * 16 + (lane & 8)) * 2;
                    uint32_t r4[4];
                    uint32_t vh0[2], vh1[2], vl0[2], vl1[2];
                    ldsm4t(r4, off + (uint32_t)(2 * KVARR) * 2);
                    vh0[0] = r4[0]; vh0[1] = r4[2];
                    vh1[0] = r4[1]; vh1[1] = r4[3];
                    ldsm4t(r4, off + (uint32_t)(3 * KVARR) * 2);
                    vl0[0] = r4[0]; vl0[1] = r4[2];
                    vl1[0] = r4[1]; vl1[1] = r4[3];
                    // pass-major (alternate accumulators)
                    mma16816(o[dt * 2],     pah[t], vh0);
                    mma16816(o[dt * 2 + 1], pah[t], vh1);
                    mma16816(o[dt * 2],     pah[t], vl0);
                    mma16816(o[dt * 2 + 1], pah[t], vl1);
                    mma16816(o[dt * 2],     pal[t], vh0);
                    mma16816(o[dt * 2 + 1], pal[t], vh1);
                }
            }
        }
    }
#undef ISSUE_KV

    const float in0 = 1.0f / l0;
    const float in1 = 1.0f / l1;
    const int r0 = q0 + wrow + (lane >> 2);
    const int bb = bh >> 4;
    const int hh = bh & 15;
#pragma unroll
    for (int j = 0; j < 8; j++) {
        int d = hh * 64 + j * 8 + 2 * (lane & 3);
        size_t i0 = ((size_t)bb * S_ + r0) * D_ + d;
        size_t i1 = i0 + (size_t)8 * D_;
        __nv_bfloat162 h2, l2;
        split2(o[j][0] * in0, o[j][1] * in0, h2, l2);
        *(__nv_bfloat162*)(g_oh + i0) = h2;
        *(__nv_bfloat162*)(g_ol + i0) = l2;
        split2(o[j][2] * in1, o[j][3] * in1, h2, l2);
        *(__nv_bfloat162*)(g_oh + i1) = h2;
        *(__nv_bfloat162*)(g_ol + i1) = l2;
    }
}

// ---------------------------------------------------------------------------
extern "C" void kernel_launch(void* const* d_in, const int* in_sizes, int n_in,
                              void* d_out, int out_size)
{
    const float* x  = (const float*)d_in[0];
    const float* Wq = (const float*)d_in[1];
    const float* bq = (const float*)d_in[2];
    const float* Wk = (const float*)d_in[3];
    const float* bk = (const float*)d_in[4];
    const float* Wv = (const float*)d_in[5];
    const float* bv = (const float*)d_in[6];
    const float* Wo = (const float*)d_in[7];
    const float* bo = (const float*)d_in[8];
    float* out = (float*)d_out;

    static int attr_set = 0;
    if (!attr_set) {
        cudaFuncSetAttribute(gemm_qkv_kernel, cudaFuncAttributeMaxDynamicSharedMemorySize, GSM);
        cudaFuncSetAttribute(gemm_o_kernel,   cudaFuncAttributeMaxDynamicSharedMemorySize, GSM);
        cudaFuncSetAttribute(attn_kernel,     cudaFuncAttributeMaxDynamicSharedMemorySize, ASM_BYTES);
        attr_set = 1;
    }

    pack_x_kernel   <<<(M_ * D_) / 1024, 256>>>(x);          // 0
    pack_wqkv_kernel<<<3 * (D_ * D_) / 1024, 256>>>(Wq, Wk, Wv); // 1
    pack_wo_kernel  <<<(D_ * D_) / 1024, 256>>>(Wo);         // 2

    gemm_qkv_kernel<<<dim3(24, 64), 256, GSM>>>(bq, bk, bv); // 3  <- ncu target

    attn_kernel<<<dim3(S_ / 128, B_ * H_), 256, ASM_BYTES>>>();  // 4

    gemm_o_kernel<<<dim3(8, 64), 256, GSM>>>(bo, out);       // 5
}